// round 10
// baseline (speedup 1.0000x reference)
#include <cuda_runtime.h>
#include <math.h>

#define Bsz 8
#define Sq  512
#define Dm  768
#define Hn  12
#define HDm 64
#define En  8
#define FFd 3072
#define TOK 4096
#define BHN 96

// ---------------- scratch (device globals; no allocations allowed) ----------
__device__ float g_h[TOK * Dm];
__device__ float g_qkv[TOK * 3 * Dm];
__device__ float g_o[TOK * Dm];
__device__ float g_h2[TOK * Dm];
__device__ float g_y1[(size_t)TOK * FFd];
__device__ int   g_routes[TOK];
__device__ int   g_cnt[En];
__device__ int   g_off[En];
__device__ int   g_cur[En];
__device__ int   g_sorted[TOK];

// ---------------- helpers ---------------------------------------------------
__device__ __forceinline__ float gelu_exact(float x) {
    return 0.5f * x * (1.0f + erff(x * 0.70710678118654752f));
}

__device__ __forceinline__ unsigned f2t(float f) {
    unsigned u;
    asm("cvt.rna.tf32.f32 %0, %1;" : "=r"(u) : "f"(f));
    return u;
}
__device__ __forceinline__ unsigned t32(unsigned u) {
    return f2t(__uint_as_float(u));
}
__device__ __forceinline__ float rtf(float f) {
    return __uint_as_float(f2t(f));
}
template<bool C> __device__ __forceinline__ unsigned cva(unsigned u) {
    return C ? t32(u) : u;
}

__device__ __forceinline__ void mma_tf32(float c[4],
                                         unsigned a0, unsigned a1, unsigned a2, unsigned a3,
                                         unsigned b0, unsigned b1) {
    asm volatile(
        "mma.sync.aligned.m16n8k8.row.col.f32.tf32.tf32.f32 "
        "{%0,%1,%2,%3},{%4,%5,%6,%7},{%8,%9},{%0,%1,%2,%3};"
        : "+f"(c[0]), "+f"(c[1]), "+f"(c[2]), "+f"(c[3])
        : "r"(a0), "r"(a1), "r"(a2), "r"(a3), "r"(b0), "r"(b1));
}

__device__ __forceinline__ void cp16(unsigned* d, const void* s) {
    unsigned sd = (unsigned)__cvta_generic_to_shared(d);
    asm volatile("cp.async.cg.shared.global [%0], [%1], 16;" :: "r"(sd), "l"(s));
}
__device__ __forceinline__ void cp16z(unsigned* d, const void* s, int pred) {
    unsigned sd = (unsigned)__cvta_generic_to_shared(d);
    int sz = pred ? 16 : 0;
    asm volatile("cp.async.cg.shared.global [%0], [%1], 16, %2;" :: "r"(sd), "l"(s), "r"(sz));
}
#define CP_COMMIT() asm volatile("cp.async.commit_group;")
#define CP_WAIT0()  asm volatile("cp.async.wait_group 0;")
#define CP_WAIT1()  asm volatile("cp.async.wait_group 1;")

// ---------------- reset counters --------------------------------------------
__global__ void reset_kernel() {
    int t = threadIdx.x;
    if (t < En) { g_cnt[t] = 0; g_cur[t] = 0; }
}

// ---------------- layernorm (optionally tf32-rounded output) ----------------
__global__ void ln_kernel(const float* __restrict__ X,
                          const float* __restrict__ gam,
                          const float* __restrict__ bet,
                          float* __restrict__ Y, int rnd) {
    int row = blockIdx.x;
    int tid = threadIdx.x;
    const float* x = X + (size_t)row * Dm;
    float v0 = x[tid], v1 = x[tid + 256], v2 = x[tid + 512];

    __shared__ float red[256];
    red[tid] = v0 + v1 + v2; __syncthreads();
    #pragma unroll
    for (int st = 128; st > 0; st >>= 1) {
        if (tid < st) red[tid] += red[tid + st];
        __syncthreads();
    }
    float mu = red[0] / (float)Dm;
    __syncthreads();

    float d0 = v0 - mu, d1 = v1 - mu, d2 = v2 - mu;
    red[tid] = d0 * d0 + d1 * d1 + d2 * d2; __syncthreads();
    #pragma unroll
    for (int st = 128; st > 0; st >>= 1) {
        if (tid < st) red[tid] += red[tid + st];
        __syncthreads();
    }
    float rstd = rsqrtf(red[0] / (float)Dm + 1e-5f);

    float* y = Y + (size_t)row * Dm;
    float o0 = d0 * rstd * gam[tid]       + bet[tid];
    float o1 = d1 * rstd * gam[tid + 256] + bet[tid + 256];
    float o2 = d2 * rstd * gam[tid + 512] + bet[tid + 512];
    if (rnd) { o0 = rtf(o0); o1 = rtf(o1); o2 = rtf(o2); }
    y[tid] = o0; y[tid + 256] = o1; y[tid + 512] = o2;
}

// =============================================================================
// tf32 GEMM: BM=256, BN=128, BK=32, 3-stage ring, 512 thr = 16 warps (4x4),
// warp tile 64x32 (R8 shape). 1 CTA/SM (159KB smem), 16 warps/SM.
// Halves B-side L2 re-reads vs BM=128.
// =============================================================================
#define BKt  32
#define BMt  256
#define ASTR 36
#define BSTR 136
#define A_SZ (BMt * ASTR)
#define B_SZ (BKt * BSTR)
#define NSTG 3
#define GEMM_SMEM (NSTG * (A_SZ + B_SZ) * 4)

#define GEMM_STAGE_MMA(Asb, Bsb, CVTA)                                         \
    _Pragma("unroll")                                                          \
    for (int ks = 0; ks < 4; ks++) {                                           \
        int kb = ks * 8;                                                       \
        unsigned af[4][4], bf[4][2];                                           \
        _Pragma("unroll")                                                      \
        for (int mt = 0; mt < 4; mt++) {                                       \
            int m = wm + mt * 16 + gid;                                        \
            af[mt][0] = cva<CVTA>((Asb)[m * ASTR + kb + tg]);                  \
            af[mt][1] = cva<CVTA>((Asb)[(m + 8) * ASTR + kb + tg]);            \
            af[mt][2] = cva<CVTA>((Asb)[m * ASTR + kb + tg + 4]);              \
            af[mt][3] = cva<CVTA>((Asb)[(m + 8) * ASTR + kb + tg + 4]);        \
        }                                                                      \
        _Pragma("unroll")                                                      \
        for (int nt = 0; nt < 4; nt++) {                                       \
            int n = wn + nt * 8 + gid;                                         \
            bf[nt][0] = t32((Bsb)[(kb + tg) * BSTR + n]);                      \
            bf[nt][1] = t32((Bsb)[(kb + tg + 4) * BSTR + n]);                  \
        }                                                                      \
        _Pragma("unroll")                                                      \
        for (int mt = 0; mt < 4; mt++)                                         \
            _Pragma("unroll")                                                  \
            for (int nt = 0; nt < 4; nt++)                                     \
                mma_tf32(acc[mt][nt], af[mt][0], af[mt][1], af[mt][2],         \
                         af[mt][3], bf[nt][0], bf[nt][1]);                     \
    }

template<bool CVTA, bool ROUT>
__global__ void __launch_bounds__(512, 1)
gemm_tf32(const float* __restrict__ A, const float* __restrict__ B,
          float* __restrict__ C, int M, int N, int K,
          const float* __restrict__ bias,
          const float* __restrict__ resid) {
    extern __shared__ unsigned smg[];
    unsigned* As = smg;
    unsigned* Bs = smg + NSTG * A_SZ;

    int tid = threadIdx.x;
    int warp = tid >> 5, lane = tid & 31;
    int gid = lane >> 2, tg = lane & 3;
    int wm = (warp >> 2) * 64, wn = (warp & 3) * 32;
    int m0 = blockIdx.y * BMt, n0 = blockIdx.x * 128;

    float acc[4][4][4];
    #pragma unroll
    for (int i = 0; i < 4; i++)
        #pragma unroll
        for (int j = 0; j < 4; j++)
            #pragma unroll
            for (int q = 0; q < 4; q++) acc[i][j][q] = 0.f;

    int raA = tid >> 3, caA = (tid & 7) * 4;    // A: 64 rows/pass, 4 passes
    int raB = tid >> 5, caB = (tid & 31) * 4;   // B: 16 rows/pass, 2 passes

    #define G_LOAD(st, gk)                                                         \
        _Pragma("unroll")                                                          \
        for (int l = 0; l < 4; l++) {                                              \
            int r = raA + l * 64;                                                  \
            cp16(&As[(st) * A_SZ + r * ASTR + caA],                                \
                 A + (size_t)(m0 + r) * K + (gk) + caA);                           \
        }                                                                          \
        _Pragma("unroll")                                                          \
        for (int l = 0; l < 2; l++) {                                              \
            int r = raB + l * 16;                                                  \
            cp16(&Bs[(st) * B_SZ + r * BSTR + caB],                                \
                 B + (size_t)((gk) + r) * N + n0 + caB);                           \
        }                                                                          \
        CP_COMMIT();

    G_LOAD(0, 0)
    G_LOAD(1, BKt)

    int nk = K / BKt;
    for (int kt = 0; kt < nk; kt++) {
        int s = kt % NSTG;
        CP_WAIT1(); __syncthreads();
        if (kt + 2 < nk) {
            int st = (kt + 2) % NSTG;
            G_LOAD(st, (kt + 2) * BKt)
        } else {
            CP_COMMIT();
        }
        GEMM_STAGE_MMA(&As[s * A_SZ], &Bs[s * B_SZ], CVTA)
    }
    #undef G_LOAD

    #pragma unroll
    for (int mt = 0; mt < 4; mt++) {
        int mA = m0 + wm + mt * 16 + gid, mB = mA + 8;
        #pragma unroll
        for (int nt = 0; nt < 4; nt++) {
            int n = n0 + wn + nt * 8 + tg * 2;
            float v0 = acc[mt][nt][0], v1 = acc[mt][nt][1];
            float v2 = acc[mt][nt][2], v3 = acc[mt][nt][3];
            if (bias) {
                float b0 = bias[n], b1 = bias[n + 1];
                v0 += b0; v1 += b1; v2 += b0; v3 += b1;
            }
            if (resid) {
                v0 += resid[(size_t)mA * N + n];
                v1 += resid[(size_t)mA * N + n + 1];
                v2 += resid[(size_t)mB * N + n];
                v3 += resid[(size_t)mB * N + n + 1];
            }
            if (ROUT) { v0 = rtf(v0); v1 = rtf(v1); v2 = rtf(v2); v3 = rtf(v3); }
            C[(size_t)mA * N + n]     = v0;
            C[(size_t)mA * N + n + 1] = v1;
            C[(size_t)mB * N + n]     = v2;
            C[(size_t)mB * N + n + 1] = v3;
        }
    }
}

// ---------------- MoE GEMM1: Y1 = round(gelu(gather(H2) @ W1[e] + b1[e])) ---
__global__ void __launch_bounds__(512, 1)
moe1_tf32(const float* __restrict__ H2,
          const float* __restrict__ W1,
          const float* __restrict__ B1,
          float* __restrict__ Y1) {
    int e = blockIdx.z;
    int cnt = g_cnt[e];
    int m0 = blockIdx.y * BMt;
    if (m0 >= cnt) return;
    int off = g_off[e];
    const float* B = W1 + (size_t)e * Dm * FFd;
    const int N = FFd, K = Dm;
    int n0 = blockIdx.x * 128;

    extern __shared__ unsigned smg[];
    unsigned* As = smg;
    unsigned* Bs = smg + NSTG * A_SZ;
    __shared__ int toks[BMt];

    int tid = threadIdx.x;
    int warp = tid >> 5, lane = tid & 31;
    int gid = lane >> 2, tg = lane & 3;
    int wm = (warp >> 2) * 64, wn = (warp & 3) * 32;
    if (tid < BMt) {
        int m = m0 + tid;
        toks[tid] = (m < cnt) ? g_sorted[off + m] : -1;
    }
    __syncthreads();

    float acc[4][4][4];
    #pragma unroll
    for (int i = 0; i < 4; i++)
        #pragma unroll
        for (int j = 0; j < 4; j++)
            #pragma unroll
            for (int q = 0; q < 4; q++) acc[i][j][q] = 0.f;

    int raA = tid >> 3, caA = (tid & 7) * 4;
    int raB = tid >> 5, caB = (tid & 31) * 4;
    int tk[4];
    #pragma unroll
    for (int l = 0; l < 4; l++) tk[l] = toks[raA + l * 64];

    #define M1_LOAD(st, gk)                                                        \
        _Pragma("unroll")                                                          \
        for (int l = 0; l < 4; l++) {                                              \
            int r = raA + l * 64;                                                  \
            cp16z(&As[(st) * A_SZ + r * ASTR + caA],                               \
                  H2 + (size_t)(tk[l] >= 0 ? tk[l] : 0) * Dm + (gk) + caA,         \
                  tk[l] >= 0);                                                     \
        }                                                                          \
        _Pragma("unroll")                                                          \
        for (int l = 0; l < 2; l++) {                                              \
            int r = raB + l * 16;                                                  \
            cp16(&Bs[(st) * B_SZ + r * BSTR + caB],                                \
                 B + (size_t)((gk) + r) * N + n0 + caB);                           \
        }                                                                          \
        CP_COMMIT();

    M1_LOAD(0, 0)
    M1_LOAD(1, BKt)

    int nk = K / BKt;
    for (int kt = 0; kt < nk; kt++) {
        int s = kt % NSTG;
        CP_WAIT1(); __syncthreads();
        if (kt + 2 < nk) {
            int st = (kt + 2) % NSTG;
            M1_LOAD(st, (kt + 2) * BKt)
        } else {
            CP_COMMIT();
        }
        GEMM_STAGE_MMA(&As[s * A_SZ], &Bs[s * B_SZ], true)
    }
    #undef M1_LOAD

    #pragma unroll
    for (int mt = 0; mt < 4; mt++) {
        int lmA = wm + mt * 16 + gid;
        int gmA = m0 + lmA, gmB = gmA + 8;
        #pragma unroll
        for (int nt = 0; nt < 4; nt++) {
            int n = wn + nt * 8 + tg * 2;
            float b0 = B1[e * FFd + n0 + n], b1 = B1[e * FFd + n0 + n + 1];
            if (gmA < cnt) {
                Y1[(size_t)(off + gmA) * FFd + n0 + n]     = rtf(gelu_exact(acc[mt][nt][0] + b0));
                Y1[(size_t)(off + gmA) * FFd + n0 + n + 1] = rtf(gelu_exact(acc[mt][nt][1] + b1));
            }
            if (gmB < cnt) {
                Y1[(size_t)(off + gmB) * FFd + n0 + n]     = rtf(gelu_exact(acc[mt][nt][2] + b0));
                Y1[(size_t)(off + gmB) * FFd + n0 + n + 1] = rtf(gelu_exact(acc[mt][nt][3] + b1));
            }
        }
    }
}

// ---------------- MoE GEMM2: out[t] += gelu(Y1 @ W2[e] + b2[e]) -------------
__global__ void __launch_bounds__(512, 1)
moe2_tf32(const float* __restrict__ Y1,
          const float* __restrict__ W2,
          const float* __restrict__ B2,
          float* __restrict__ OUT) {
    int e = blockIdx.z;
    int cnt = g_cnt[e];
    int m0 = blockIdx.y * BMt;
    if (m0 >= cnt) return;
    int off = g_off[e];
    const float* B = W2 + (size_t)e * FFd * Dm;
    const int N = Dm, K = FFd;
    int n0 = blockIdx.x * 128;

    extern __shared__ unsigned smg[];
    unsigned* As = smg;
    unsigned* Bs = smg + NSTG * A_SZ;
    __shared__ int toks[BMt];

    int tid = threadIdx.x;
    int warp = tid >> 5, lane = tid & 31;
    int gid = lane >> 2, tg = lane & 3;
    int wm = (warp >> 2) * 64, wn = (warp & 3) * 32;
    if (tid < BMt) {
        int m = m0 + tid;
        toks[tid] = (m < cnt) ? g_sorted[off + m] : -1;
    }
    __syncthreads();

    float acc[4][4][4];
    #pragma unroll
    for (int i = 0; i < 4; i++)
        #pragma unroll
        for (int j = 0; j < 4; j++)
            #pragma unroll
            for (int q = 0; q < 4; q++) acc[i][j][q] = 0.f;

    int raA = tid >> 3, caA = (tid & 7) * 4;
    int raB = tid >> 5, caB = (tid & 31) * 4;
    int ok[4];
    #pragma unroll
    for (int l = 0; l < 4; l++) ok[l] = (m0 + raA + l * 64) < cnt;

    #define M2_LOAD(st, gk)                                                        \
        _Pragma("unroll")                                                          \
        for (int l = 0; l < 4; l++) {                                              \
            int r = raA + l * 64;                                                  \
            cp16z(&As[(st) * A_SZ + r * ASTR + caA],                               \
                  Y1 + (size_t)(off + (ok[l] ? m0 + r : 0)) * FFd + (gk) + caA,    \
                  ok[l]);                                                          \
        }                                                                          \
        _Pragma("unroll")                                                          \
        for (int l = 0; l < 2; l++) {                                              \
            int r = raB + l * 16;                                                  \
            cp16(&Bs[(st) * B_SZ + r * BSTR + caB],                                \
                 B + (size_t)((gk) + r) * N + n0 + caB);                           \
        }                                                                          \
        CP_COMMIT();

    M2_LOAD(0, 0)
    M2_LOAD(1, BKt)

    int nk = K / BKt;
    for (int kt = 0; kt < nk; kt++) {
        int s = kt % NSTG;
        CP_WAIT1(); __syncthreads();
        if (kt + 2 < nk) {
            int st = (kt + 2) % NSTG;
            M2_LOAD(st, (kt + 2) * BKt)
        } else {
            CP_COMMIT();
        }
        GEMM_STAGE_MMA(&As[s * A_SZ], &Bs[s * B_SZ], false)   // Y1 pre-rounded
    }
    #undef M2_LOAD

    #pragma unroll
    for (int mt = 0; mt < 4; mt++) {
        int lmA = wm + mt * 16 + gid;
        int gmA = m0 + lmA, gmB = gmA + 8;
        int tA = toks[lmA], tB = toks[lmA + 8];
        #pragma unroll
        for (int nt = 0; nt < 4; nt++) {
            int n = wn + nt * 8 + tg * 2;
            float b0 = B2[e * Dm + n0 + n], b1 = B2[e * Dm + n0 + n + 1];
            if (gmA < cnt) {
                OUT[(size_t)tA * Dm + n0 + n]     += gelu_exact(acc[mt][nt][0] + b0);
                OUT[(size_t)tA * Dm + n0 + n + 1] += gelu_exact(acc[mt][nt][1] + b1);
            }
            if (gmB < cnt) {
                OUT[(size_t)tB * Dm + n0 + n]     += gelu_exact(acc[mt][nt][2] + b0);
                OUT[(size_t)tB * Dm + n0 + n + 1] += gelu_exact(acc[mt][nt][3] + b1);
            }
        }
    }
}

// =============================================================================
// Fused flash attention, K/V double-buffered (unchanged).
// =============================================================================
#define QSTR 68
#define VSTR 72
#define FA_SMEM ((64 * QSTR + 2 * 64 * QSTR + 2 * 64 * VSTR) * 4)

__global__ void flash_tf32(const float* __restrict__ QKV, float* __restrict__ O) {
    extern __shared__ unsigned sm[];
    unsigned* Qs = sm;
    unsigned* Ks = sm + 64 * QSTR;
    unsigned* Vs = sm + 64 * QSTR + 2 * 64 * QSTR;

    int bh = blockIdx.y;
    int b = bh / Hn, h = bh % Hn;
    int m0 = blockIdx.x * 64;
    int tid = threadIdx.x;
    int warp = tid >> 5, lane = tid & 31;
    int gid = lane >> 2, tg = lane & 3;
    int wm = warp * 16;

    #pragma unroll
    for (int l = 0; l < 8; l++) {
        int idx = tid + l * 128, r = idx >> 4, c4 = (idx & 15) * 4;
        cp16(&Qs[r * QSTR + c4],
             QKV + (size_t)(b * Sq + m0 + r) * 2304 + h * HDm + c4);
    }
    CP_COMMIT(); CP_WAIT0(); __syncthreads();

    unsigned aq[8][4];
    #pragma unroll
    for (int k8 = 0; k8 < 8; k8++) {
        int kb = k8 * 8;
        aq[k8][0] = Qs[(wm + gid) * QSTR + kb + tg];
        aq[k8][1] = Qs[(wm + gid + 8) * QSTR + kb + tg];
        aq[k8][2] = Qs[(wm + gid) * QSTR + kb + tg + 4];
        aq[k8][3] = Qs[(wm + gid + 8) * QSTR + kb + tg + 4];
    }
    __syncthreads();

    #define FA_LOAD_KV(chunk, buf)                                                 \
        _Pragma("unroll")                                                          \
        for (int l = 0; l < 8; l++) {                                              \
            int idx = tid + l * 128, r = idx >> 4, c4 = (idx & 15) * 4;            \
            cp16(&Ks[(buf) * 64 * QSTR + r * QSTR + c4],                           \
                 QKV + (size_t)(b * Sq + (chunk) * 64 + r) * 2304 + Dm + h * HDm + c4); \
        }                                                                          \
        _Pragma("unroll")                                                          \
        for (int l = 0; l < 8; l++) {                                              \
            int idx = tid + l * 128, r = idx >> 4, c4 = (idx & 15) * 4;            \
            cp16(&Vs[(buf) * 64 * VSTR + r * VSTR + c4],                           \
                 QKV + (size_t)(b * Sq + (chunk) * 64 + r) * 2304 + 2 * Dm + h * HDm + c4); \
        }                                                                          \
        CP_COMMIT();

    float mr0 = -1e30f, mr1 = -1e30f, lr0 = 0.f, lr1 = 0.f;
    float o[8][4];
    #pragma unroll
    for (int nt = 0; nt < 8; nt++)
        #pragma unroll
        for (int q = 0; q < 4; q++) o[nt][q] = 0.f;

    FA_LOAD_KV(0, 0)

    for (int c = 0; c < 8; c++) {
        int buf = c & 1;
        if (c + 1 < 8) {
            FA_LOAD_KV(c + 1, buf ^ 1)
            CP_WAIT1();
        } else {
            CP_WAIT0();
        }
        __syncthreads();
        unsigned* Kb = Ks + buf * 64 * QSTR;
        unsigned* Vb = Vs + buf * 64 * VSTR;

        float s[8][4];
        #pragma unroll
        for (int nt = 0; nt < 8; nt++)
            #pragma unroll
            for (int q = 0; q < 4; q++) s[nt][q] = 0.f;
        #pragma unroll
        for (int k8 = 0; k8 < 8; k8++) {
            int kb = k8 * 8;
            #pragma unroll
            for (int nt = 0; nt < 8; nt++) {
                int n = nt * 8 + gid;
                unsigned b0 = Kb[n * QSTR + kb + tg];
                unsigned b1 = Kb[n * QSTR + kb + tg + 4];
                mma_tf32(s[nt], aq[k8][0], aq[k8][1], aq[k8][2], aq[k8][3], b0, b1);
            }
        }

        const float sc = 0.125f;
        float mx0 = -1e30f, mx1 = -1e30f;
        #pragma unroll
        for (int nt = 0; nt < 8; nt++) {
            s[nt][0] *= sc; s[nt][1] *= sc; s[nt][2] *= sc; s[nt][3] *= sc;
            mx0 = fmaxf(mx0, fmaxf(s[nt][0], s[nt][1]));
            mx1 = fmaxf(mx1, fmaxf(s[nt][2], s[nt][3]));
        }
        mx0 = fmaxf(mx0, __shfl_xor_sync(0xffffffffu, mx0, 1));
        mx0 = fmaxf(mx0, __shfl_xor_sync(0xffffffffu, mx0, 2));
        mx1 = fmaxf(mx1, __shfl_xor_sync(0xffffffffu, mx1, 1));
        mx1 = fmaxf(mx1, __shfl_xor_sync(0xffffffffu, mx1, 2));
        float mn0 = fmaxf(mr0, mx0), mn1 = fmaxf(mr1, mx1);
        float a0 = __expf(mr0 - mn0), a1 = __expf(mr1 - mn1);
        float sum0 = 0.f, sum1 = 0.f;
        #pragma unroll
        for (int nt = 0; nt < 8; nt++) {
            s[nt][0] = __expf(s[nt][0] - mn0);
            s[nt][1] = __expf(s[nt][1] - mn0);
            s[nt][2] = __expf(s[nt][2] - mn1);
            s[nt][3] = __expf(s[nt][3] - mn1);
            sum0 += s[nt][0] + s[nt][1];
            sum1 += s[nt][2] + s[nt][3];
        }
        sum0 += __shfl_xor_sync(0xffffffffu, sum0, 1);
        sum0 += __shfl_xor_sync(0xffffffffu, sum0, 2);
        sum1 += __shfl_xor_sync(0xffffffffu, sum1, 1);
        sum1 += __shfl_xor_sync(0xffffffffu, sum1, 2);
        lr0 = lr0 * a0 + sum0;
        lr1 = lr1 * a1 + sum1;
        mr0 = mn0; mr1 = mn1;
        #pragma unroll
        for (int nt = 0; nt < 8; nt++) {
            o[nt][0] *= a0; o[nt][1] *= a0;
            o[nt][2] *= a1; o[nt][3] *= a1;
        }

        unsigned* Ps = Qs;
        #pragma unroll
        for (int nt = 0; nt < 8; nt++) {
            int cc = nt * 8 + tg * 2;
            Ps[(wm + gid) * QSTR + cc]         = f2t(s[nt][0]);
            Ps[(wm + gid) * QSTR + cc + 1]     = f2t(s[nt][1]);
            Ps[(wm + gid + 8) * QSTR + cc]     = f2t(s[nt][2]);
            Ps[(wm + gid + 8) * QSTR + cc + 1] = f2t(s[nt][3]);
        }
        __syncwarp();

        #pragma unroll
        for (int kb = 0; kb < 64; kb += 8) {
            unsigned p0 = Ps[(wm + gid) * QSTR + kb + tg];
            unsigned p1 = Ps[(wm + gid + 8) * QSTR + kb + tg];
            unsigned p2 = Ps[(wm + gid) * QSTR + kb + tg + 4];
            unsigned p3 = Ps[(wm + gid + 8) * QSTR + kb + tg + 4];
            #pragma unroll
            for (int nt = 0; nt < 8; nt++) {
                int n = nt * 8 + gid;
                unsigned v0 = Vb[(kb + tg) * VSTR + n];
                unsigned v1 = Vb[(kb + tg + 4) * VSTR + n];
                mma_tf32(o[nt], p0, p1, p2, p3, v0, v1);
            }
        }
        __syncthreads();
    }
    #undef FA_LOAD_KV

    float inv0 = 1.0f / lr0, inv1 = 1.0f / lr1;
    int rA = b * Sq + m0 + wm + gid, rB = rA + 8;
    #pragma unroll
    for (int nt = 0; nt < 8; nt++) {
        int cc = h * HDm + nt * 8 + tg * 2;
        O[(size_t)rA * Dm + cc]     = rtf(o[nt][0] * inv0);
        O[(size_t)rA * Dm + cc + 1] = rtf(o[nt][1] * inv0);
        O[(size_t)rB * Dm + cc]     = rtf(o[nt][2] * inv1);
        O[(size_t)rB * Dm + cc + 1] = rtf(o[nt][3] * inv1);
    }
}

// ---------------- router (exact fp32 logits) ----------------------------------
__global__ void route_kernel(const float* __restrict__ H2,
                             const float* __restrict__ SW,
                             const float* __restrict__ SB) {
    int warp = (blockIdx.x * blockDim.x + threadIdx.x) >> 5;
    int lane = threadIdx.x & 31;
    if (warp >= TOK) return;
    const float* hrow = H2 + (size_t)warp * Dm;
    float acc[En];
    #pragma unroll
    for (int e = 0; e < En; e++) acc[e] = 0.f;
    for (int d = lane; d < Dm; d += 32) {
        float hv = hrow[d];
        const float* w = SW + d * En;
        #pragma unroll
        for (int e = 0; e < En; e++) acc[e] += hv * w[e];
    }
    #pragma unroll
    for (int e = 0; e < En; e++)
        #pragma unroll
        for (int o = 16; o; o >>= 1)
            acc[e] += __shfl_xor_sync(0xffffffffu, acc[e], o);
    if (lane == 0) {
        float best = acc[0] + SB[0];
        int be = 0;
        #pragma unroll
        for (int e = 1; e < En; e++) {
            float v = acc[e] + SB[e];
            if (v > best) { best = v; be = e; }
        }
        g_routes[warp] = be;
        atomicAdd(&g_cnt[be], 1);
    }
}

__global__ void offsets_kernel() {
    if (threadIdx.x == 0) {
        int acc = 0;
        for (int e = 0; e < En; e++) { g_off[e] = acc; acc += g_cnt[e]; }
    }
}

__global__ void scatter_kernel() {
    int t = blockIdx.x * blockDim.x + threadIdx.x;
    if (t >= TOK) return;
    int e = g_routes[t];
    int pos = atomicAdd(&g_cur[e], 1);
    g_sorted[g_off[e] + pos] = t;
}

// ---------------- launch ------------------------------------------------------
extern "C" void kernel_launch(void* const* d_in, const int* in_sizes, int n_in,
                              void* d_out, int out_size) {
    const float* x       = (const float*)d_in[0];
    // d_in[1] = indexes_list (unused by reference math)
    const float* ln1_g   = (const float*)d_in[2];
    const float* ln1_b   = (const float*)d_in[3];
    const float* qkv_w   = (const float*)d_in[4];
    const float* proj_w  = (const float*)d_in[5];
    const float* proj_b  = (const float*)d_in[6];
    const float* ln2_g   = (const float*)d_in[7];
    const float* ln2_b   = (const float*)d_in[8];
    const float* sw_w    = (const float*)d_in[9];
    const float* sw_b    = (const float*)d_in[10];
    const float* w1      = (const float*)d_in[11];
    const float* b1      = (const float*)d_in[12];
    const float* w2      = (const float*)d_in[13];
    const float* b2      = (const float*)d_in[14];
    float* out = (float*)d_out;

    float *gh, *gqkv, *go, *gh2, *gy1;
    cudaGetSymbolAddress((void**)&gh,   g_h);
    cudaGetSymbolAddress((void**)&gqkv, g_qkv);
    cudaGetSymbolAddress((void**)&go,   g_o);
    cudaGetSymbolAddress((void**)&gh2,  g_h2);
    cudaGetSymbolAddress((void**)&gy1,  g_y1);

    static int smem_set = 0;
    if (!smem_set) {
        cudaFuncSetAttribute(flash_tf32, cudaFuncAttributeMaxDynamicSharedMemorySize, FA_SMEM);
        cudaFuncSetAttribute(gemm_tf32<false, true>,  cudaFuncAttributeMaxDynamicSharedMemorySize, GEMM_SMEM);
        cudaFuncSetAttribute(gemm_tf32<false, false>, cudaFuncAttributeMaxDynamicSharedMemorySize, GEMM_SMEM);
        cudaFuncSetAttribute(moe1_tf32, cudaFuncAttributeMaxDynamicSharedMemorySize, GEMM_SMEM);
        cudaFuncSetAttribute(moe2_tf32, cudaFuncAttributeMaxDynamicSharedMemorySize, GEMM_SMEM);
        smem_set = 1;
    }

    reset_kernel<<<1, 32>>>();

    // ln1 -> tf32-rounded (feeds qkv GEMM A only)
    ln_kernel<<<TOK, 256>>>(x, ln1_g, ln1_b, gh, 1);
    // qkv = h @ qkv_w, output rounded (feeds flash only)
    gemm_tf32<false, true><<<dim3(2304 / 128, TOK / BMt), 512, GEMM_SMEM>>>(
        gh, qkv_w, gqkv, TOK, 2304, Dm, nullptr, nullptr);
    // fused attention; output rounded (feeds proj A only)
    flash_tf32<<<dim3(Sq / 64, BHN), 128, FA_SMEM>>>(gqkv, go);
    // xmid = x + o @ proj_w + proj_b -> d_out (exact fp32: final-output term)
    gemm_tf32<false, false><<<dim3(Dm / 128, TOK / BMt), 512, GEMM_SMEM>>>(
        go, proj_w, out, TOK, Dm, Dm, proj_b, x);
    // ln2 -> exact fp32 (router needs exact logits; moe1 cvts in-kernel)
    ln_kernel<<<TOK, 256>>>(out, ln2_g, ln2_b, gh2, 0);
    // routing
    route_kernel<<<512, 256>>>(gh2, sw_w, sw_b);
    offsets_kernel<<<1, 32>>>();
    scatter_kernel<<<TOK / 256, 256>>>();
    // MoE expert GEMMs
    moe1_tf32<<<dim3(FFd / 128, TOK / BMt, En), 512, GEMM_SMEM>>>(gh2, w1, b1, gy1);
    moe2_tf32<<<dim3(Dm / 128, TOK / BMt, En), 512, GEMM_SMEM>>>(gy1, w2, b2, out);
}

// round 14
// speedup vs baseline: 1.2728x; 1.2728x over previous
#include <cuda_runtime.h>
#include <cuda_fp16.h>
#include <stdint.h>
#include <math.h>

#define Bsz 8
#define Sq  512
#define Dm  768
#define Hn  12
#define HDm 64
#define En  8
#define FFd 3072
#define TOK 4096
#define BHN 96
#define BKh 32

// ---------------- scratch (device globals; no allocations allowed) ----------
__device__ __half g_h[TOK * Dm];             // ln1 out (f16)
__device__ float  g_qkv[TOK * 3 * Dm];       // tf32-grid fp32 (flash operand)
__device__ __half g_o[TOK * Dm];             // flash out (f16)
__device__ float  g_h2[TOK * Dm];            // ln2 out exact (router)
__device__ __half g_hh[TOK * Dm];            // ln2 out f16 (moe1 A)
__device__ __half g_y1[(size_t)TOK * FFd];   // moe hidden (f16)
__device__ __half g_qkvT[3 * Dm * Dm];       // [2304][768] f16
__device__ __half g_projT[Dm * Dm];          // [768][768] f16
__device__ __half g_w1T[(size_t)En * FFd * Dm];  // per e: [3072][768] f16
__device__ __half g_w2T[(size_t)En * Dm * FFd];  // per e: [768][3072] f16
__device__ int    g_routes[TOK];
__device__ int    g_cnt[En];
__device__ int    g_off[En];
__device__ int    g_cur[En];
__device__ int    g_sorted[TOK];

// ---------------- helpers ---------------------------------------------------
__device__ __forceinline__ float gelu_exact(float x) {
    return 0.5f * x * (1.0f + erff(x * 0.70710678118654752f));
}
__device__ __forceinline__ unsigned f2t(float f) {
    unsigned u;
    asm("cvt.rna.tf32.f32 %0, %1;" : "=r"(u) : "f"(f));
    return u;
}
__device__ __forceinline__ float rtf(float f) { return __uint_as_float(f2t(f)); }

__device__ __forceinline__ void mma_tf32(float c[4],
                                         unsigned a0, unsigned a1, unsigned a2, unsigned a3,
                                         unsigned b0, unsigned b1) {
    asm volatile(
        "mma.sync.aligned.m16n8k8.row.col.f32.tf32.tf32.f32 "
        "{%0,%1,%2,%3},{%4,%5,%6,%7},{%8,%9},{%0,%1,%2,%3};"
        : "+f"(c[0]), "+f"(c[1]), "+f"(c[2]), "+f"(c[3])
        : "r"(a0), "r"(a1), "r"(a2), "r"(a3), "r"(b0), "r"(b1));
}

__device__ __forceinline__ void mma_f16(float c[4],
                                        unsigned a0, unsigned a1, unsigned a2, unsigned a3,
                                        unsigned b0, unsigned b1) {
    asm volatile(
        "mma.sync.aligned.m16n8k16.row.col.f32.f16.f16.f32 "
        "{%0,%1,%2,%3},{%4,%5,%6,%7},{%8,%9},{%0,%1,%2,%3};"
        : "+f"(c[0]), "+f"(c[1]), "+f"(c[2]), "+f"(c[3])
        : "r"(a0), "r"(a1), "r"(a2), "r"(a3), "r"(b0), "r"(b1));
}

__device__ __forceinline__ void cp16(void* d, const void* s) {
    unsigned sd = (unsigned)__cvta_generic_to_shared(d);
    asm volatile("cp.async.cg.shared.global [%0], [%1], 16;" :: "r"(sd), "l"(s));
}
__device__ __forceinline__ void cp16z(void* d, const void* s, int pred) {
    unsigned sd = (unsigned)__cvta_generic_to_shared(d);
    int sz = pred ? 16 : 0;
    asm volatile("cp.async.cg.shared.global [%0], [%1], 16, %2;" :: "r"(sd), "l"(s), "r"(sz));
}
__device__ __forceinline__ void cp_commit() { asm volatile("cp.async.commit_group;"); }
__device__ __forceinline__ void cp_wait0()  { asm volatile("cp.async.wait_group 0;"); }
__device__ __forceinline__ void cp_wait1()  { asm volatile("cp.async.wait_group 1;"); }

__device__ __forceinline__ __half2 f2h2(float a, float b) {
    return __halves2half2(__float2half_rn(a), __float2half_rn(b));
}

// ---------------- reset counters --------------------------------------------
__global__ void reset_kernel() {
    int t = threadIdx.x;
    if (t < En) { g_cnt[t] = 0; g_cur[t] = 0; }
}

// ---------------- transpose + f16 convert: Wt[n][k] = h(W[k][n]) ------------
__global__ void transpose_h(const float* __restrict__ W, __half* __restrict__ Wt,
                            int K, int N) {
    size_t eo = (size_t)blockIdx.z * K * N;
    W += eo; Wt += eo;
    __shared__ float t[32][33];
    int n0 = blockIdx.x * 32, k0 = blockIdx.y * 32;
    int tx = threadIdx.x, ty = threadIdx.y;
    #pragma unroll
    for (int l = 0; l < 4; l++)
        t[ty + l * 8][tx] = W[(size_t)(k0 + ty + l * 8) * N + n0 + tx];
    __syncthreads();
    #pragma unroll
    for (int l = 0; l < 4; l++)
        Wt[(size_t)(n0 + ty + l * 8) * K + k0 + tx] = __float2half_rn(t[tx][ty + l * 8]);
}

// ---------------- layernorm: outputs fp32 (opt) and/or f16 (opt) ------------
__global__ void ln_kernel(const float* __restrict__ X,
                          const float* __restrict__ gam,
                          const float* __restrict__ bet,
                          float* __restrict__ Yf, __half* __restrict__ Yh) {
    int row = blockIdx.x;
    int tid = threadIdx.x;
    const float* x = X + (size_t)row * Dm;
    float v0 = x[tid], v1 = x[tid + 256], v2 = x[tid + 512];

    __shared__ float red[256];
    red[tid] = v0 + v1 + v2; __syncthreads();
    #pragma unroll
    for (int st = 128; st > 0; st >>= 1) {
        if (tid < st) red[tid] += red[tid + st];
        __syncthreads();
    }
    float mu = red[0] / (float)Dm;
    __syncthreads();

    float d0 = v0 - mu, d1 = v1 - mu, d2 = v2 - mu;
    red[tid] = d0 * d0 + d1 * d1 + d2 * d2; __syncthreads();
    #pragma unroll
    for (int st = 128; st > 0; st >>= 1) {
        if (tid < st) red[tid] += red[tid + st];
        __syncthreads();
    }
    float rstd = rsqrtf(red[0] / (float)Dm + 1e-5f);

    float o0 = d0 * rstd * gam[tid]       + bet[tid];
    float o1 = d1 * rstd * gam[tid + 256] + bet[tid + 256];
    float o2 = d2 * rstd * gam[tid + 512] + bet[tid + 512];
    if (Yf) {
        float* y = Yf + (size_t)row * Dm;
        y[tid] = o0; y[tid + 256] = o1; y[tid + 512] = o2;
    }
    if (Yh) {
        __half* y = Yh + (size_t)row * Dm;
        y[tid]       = __float2half_rn(o0);
        y[tid + 256] = __float2half_rn(o1);
        y[tid + 512] = __float2half_rn(o2);
    }
}

// =============================================================================
// f16 GEMM: BM=128, BN=128, BK=32, 3-stage cp.async ring, 256 thr = 8 warps
// (2x4), warp tile 64x32 via m16n8k16. A [m][k] f16, B=Wt [n][k] f16.
// smem rows: 16 half2-words padded to 20 (conflict-free fragment loads).
// =============================================================================
#define HSTR 20
#define HS_SZ (128 * HSTR)
#define GEMM_SMEM_H (2 * 3 * HS_SZ * 4)

__device__ __forceinline__ void h_load(unsigned* As, unsigned* Bs, int st, int gk,
                                       const __half* Arow, int okA,
                                       const __half* Brow, int lr, int lw) {
    cp16z(&As[st * HS_SZ + lr * HSTR + lw],     Arow + gk + lw * 2,     okA);
    cp16z(&As[st * HS_SZ + lr * HSTR + lw + 4], Arow + gk + lw * 2 + 8, okA);
    cp16(&Bs[st * HS_SZ + lr * HSTR + lw],      Brow + gk + lw * 2);
    cp16(&Bs[st * HS_SZ + lr * HSTR + lw + 4],  Brow + gk + lw * 2 + 8);
    cp_commit();
}

__device__ __forceinline__ void h_mma_stage(const unsigned* As, const unsigned* Bs,
                                            float acc[4][4][4],
                                            int wm, int wn, int gid, int tg) {
    #pragma unroll
    for (int ks = 0; ks < 2; ks++) {
        int kwb = ks * 8;
        unsigned af[4][4], bf[4][2];
        #pragma unroll
        for (int mt = 0; mt < 4; mt++) {
            int m = wm + mt * 16 + gid;
            af[mt][0] = As[m * HSTR + kwb + tg];
            af[mt][1] = As[(m + 8) * HSTR + kwb + tg];
            af[mt][2] = As[m * HSTR + kwb + tg + 4];
            af[mt][3] = As[(m + 8) * HSTR + kwb + tg + 4];
        }
        #pragma unroll
        for (int nt = 0; nt < 4; nt++) {
            int n = wn + nt * 8 + gid;
            bf[nt][0] = Bs[n * HSTR + kwb + tg];
            bf[nt][1] = Bs[n * HSTR + kwb + tg + 4];
        }
        #pragma unroll
        for (int mt = 0; mt < 4; mt++)
            #pragma unroll
            for (int nt = 0; nt < 4; nt++)
                mma_f16(acc[mt][nt], af[mt][0], af[mt][1], af[mt][2], af[mt][3],
                        bf[nt][0], bf[nt][1]);
    }
}

// ---- dense f16 GEMM: C(fp32) = A @ Wt^T (+bias)(+resid)(tf32-round) ---------
__global__ void __launch_bounds__(256)
gemm_f16(const __half* __restrict__ A, const __half* __restrict__ Wt,
         float* __restrict__ C, int N, int K,
         const float* __restrict__ bias, const float* __restrict__ resid, int rnd) {
    extern __shared__ unsigned smg[];
    unsigned* As = smg;
    unsigned* Bs = smg + 3 * HS_SZ;
    int tid = threadIdx.x, warp = tid >> 5, lane = tid & 31;
    int gid = lane >> 2, tg = lane & 3;
    int wm = (warp >> 2) * 64, wn = (warp & 3) * 32;
    int m0 = blockIdx.y * 128, n0 = blockIdx.x * 128;

    float acc[4][4][4];
    #pragma unroll
    for (int i = 0; i < 4; i++)
        #pragma unroll
        for (int j = 0; j < 4; j++)
            #pragma unroll
            for (int q = 0; q < 4; q++) acc[i][j][q] = 0.f;

    int lr = tid >> 1, lw = (tid & 1) * 8;
    const __half* Arow = A + (size_t)(m0 + lr) * K;
    const __half* Brow = Wt + (size_t)(n0 + lr) * K;

    h_load(As, Bs, 0, 0,   Arow, 1, Brow, lr, lw);
    h_load(As, Bs, 1, BKh, Arow, 1, Brow, lr, lw);

    int nk = K / BKh;
    for (int kt = 0; kt < nk; kt++) {
        int s = kt % 3;
        cp_wait1(); __syncthreads();
        if (kt + 2 < nk) {
            h_load(As, Bs, (kt + 2) % 3, (kt + 2) * BKh, Arow, 1, Brow, lr, lw);
        } else {
            cp_commit();
        }
        h_mma_stage(&As[s * HS_SZ], &Bs[s * HS_SZ], acc, wm, wn, gid, tg);
    }

    #pragma unroll
    for (int mt = 0; mt < 4; mt++) {
        int mA = m0 + wm + mt * 16 + gid, mB = mA + 8;
        #pragma unroll
        for (int nt = 0; nt < 4; nt++) {
            int n = n0 + wn + nt * 8 + tg * 2;
            float v0 = acc[mt][nt][0], v1 = acc[mt][nt][1];
            float v2 = acc[mt][nt][2], v3 = acc[mt][nt][3];
            if (bias) {
                float b0 = bias[n], b1 = bias[n + 1];
                v0 += b0; v1 += b1; v2 += b0; v3 += b1;
            }
            if (resid) {
                v0 += resid[(size_t)mA * N + n];
                v1 += resid[(size_t)mA * N + n + 1];
                v2 += resid[(size_t)mB * N + n];
                v3 += resid[(size_t)mB * N + n + 1];
            }
            if (rnd) { v0 = rtf(v0); v1 = rtf(v1); v2 = rtf(v2); v3 = rtf(v3); }
            C[(size_t)mA * N + n]     = v0;
            C[(size_t)mA * N + n + 1] = v1;
            C[(size_t)mB * N + n]     = v2;
            C[(size_t)mB * N + n + 1] = v3;
        }
    }
}

// ---- MoE GEMM1: Y1(f16) = gelu(gather(Hh) @ w1T^T + b1) ---------------------
__global__ void __launch_bounds__(256)
moe1_f16(const __half* __restrict__ Hh, const __half* __restrict__ W1T,
         const float* __restrict__ B1, __half* __restrict__ Y1) {
    int e = blockIdx.z;
    int cnt = g_cnt[e];
    int m0 = blockIdx.y * 128;
    if (m0 >= cnt) return;
    int off = g_off[e];

    extern __shared__ unsigned smg[];
    unsigned* As = smg;
    unsigned* Bs = smg + 3 * HS_SZ;
    __shared__ int toks[128];
    int tid = threadIdx.x, warp = tid >> 5, lane = tid & 31;
    int gid = lane >> 2, tg = lane & 3;
    int wm = (warp >> 2) * 64, wn = (warp & 3) * 32;
    if (tid < 128) {
        int m = m0 + tid;
        toks[tid] = (m < cnt) ? g_sorted[off + m] : -1;
    }
    __syncthreads();

    float acc[4][4][4];
    #pragma unroll
    for (int i = 0; i < 4; i++)
        #pragma unroll
        for (int j = 0; j < 4; j++)
            #pragma unroll
            for (int q = 0; q < 4; q++) acc[i][j][q] = 0.f;

    int n0 = blockIdx.x * 128;
    int lr = tid >> 1, lw = (tid & 1) * 8;
    int tok = toks[lr];
    const __half* Arow = Hh + (size_t)(tok >= 0 ? tok : 0) * Dm;
    const __half* Brow = W1T + (size_t)e * FFd * Dm + (size_t)(n0 + lr) * Dm;
    int okA = tok >= 0;

    h_load(As, Bs, 0, 0,   Arow, okA, Brow, lr, lw);
    h_load(As, Bs, 1, BKh, Arow, okA, Brow, lr, lw);

    int nk = Dm / BKh;
    for (int kt = 0; kt < nk; kt++) {
        int s = kt % 3;
        cp_wait1(); __syncthreads();
        if (kt + 2 < nk) {
            h_load(As, Bs, (kt + 2) % 3, (kt + 2) * BKh, Arow, okA, Brow, lr, lw);
        } else {
            cp_commit();
        }
        h_mma_stage(&As[s * HS_SZ], &Bs[s * HS_SZ], acc, wm, wn, gid, tg);
    }

    #pragma unroll
    for (int mt = 0; mt < 4; mt++) {
        int gmA = m0 + wm + mt * 16 + gid, gmB = gmA + 8;
        #pragma unroll
        for (int nt = 0; nt < 4; nt++) {
            int n = n0 + wn + nt * 8 + tg * 2;
            float b0 = B1[e * FFd + n], b1 = B1[e * FFd + n + 1];
            if (gmA < cnt) {
                float v0 = gelu_exact(acc[mt][nt][0] + b0);
                float v1 = gelu_exact(acc[mt][nt][1] + b1);
                *(__half2*)&Y1[(size_t)(off + gmA) * FFd + n] = f2h2(v0, v1);
            }
            if (gmB < cnt) {
                float v2 = gelu_exact(acc[mt][nt][2] + b0);
                float v3 = gelu_exact(acc[mt][nt][3] + b1);
                *(__half2*)&Y1[(size_t)(off + gmB) * FFd + n] = f2h2(v2, v3);
            }
        }
    }
}

// ---- MoE GEMM2: OUT(fp32)[tok] += gelu(Y1 @ w2T^T + b2) ---------------------
__global__ void __launch_bounds__(256)
moe2_f16(const __half* __restrict__ Y1, const __half* __restrict__ W2T,
         const float* __restrict__ B2, float* __restrict__ OUT) {
    int e = blockIdx.z;
    int cnt = g_cnt[e];
    int m0 = blockIdx.y * 128;
    if (m0 >= cnt) return;
    int off = g_off[e];

    extern __shared__ unsigned smg[];
    unsigned* As = smg;
    unsigned* Bs = smg + 3 * HS_SZ;
    __shared__ int toks[128];
    int tid = threadIdx.x, warp = tid >> 5, lane = tid & 31;
    int gid = lane >> 2, tg = lane & 3;
    int wm = (warp >> 2) * 64, wn = (warp & 3) * 32;
    if (tid < 128) {
        int m = m0 + tid;
        toks[tid] = (m < cnt) ? g_sorted[off + m] : -1;
    }
    __syncthreads();

    float acc[4][4][4];
    #pragma unroll
    for (int i = 0; i < 4; i++)
        #pragma unroll
        for (int j = 0; j < 4; j++)
            #pragma unroll
            for (int q = 0; q < 4; q++) acc[i][j][q] = 0.f;

    int n0 = blockIdx.x * 128;
    int lr = tid >> 1, lw = (tid & 1) * 8;
    int okA = (m0 + lr) < cnt;
    const __half* Arow = Y1 + (size_t)(off + (okA ? m0 + lr : 0)) * FFd;
    const __half* Brow = W2T + (size_t)e * Dm * FFd + (size_t)(n0 + lr) * FFd;

    h_load(As, Bs, 0, 0,   Arow, okA, Brow, lr, lw);
    h_load(As, Bs, 1, BKh, Arow, okA, Brow, lr, lw);

    int nk = FFd / BKh;
    for (int kt = 0; kt < nk; kt++) {
        int s = kt % 3;
        cp_wait1(); __syncthreads();
        if (kt + 2 < nk) {
            h_load(As, Bs, (kt + 2) % 3, (kt + 2) * BKh, Arow, okA, Brow, lr, lw);
        } else {
            cp_commit();
        }
        h_mma_stage(&As[s * HS_SZ], &Bs[s * HS_SZ], acc, wm, wn, gid, tg);
    }

    #pragma unroll
    for (int mt = 0; mt < 4; mt++) {
        int lmA = wm + mt * 16 + gid;
        int gmA = m0 + lmA, gmB = gmA + 8;
        int tA = toks[lmA], tB = toks[lmA + 8];
        #pragma unroll
        for (int nt = 0; nt < 4; nt++) {
            int n = n0 + wn + nt * 8 + tg * 2;
            float b0 = B2[e * Dm + n], b1 = B2[e * Dm + n + 1];
            if (gmA < cnt) {
                OUT[(size_t)tA * Dm + n]     += gelu_exact(acc[mt][nt][0] + b0);
                OUT[(size_t)tA * Dm + n + 1] += gelu_exact(acc[mt][nt][1] + b1);
            }
            if (gmB < cnt) {
                OUT[(size_t)tB * Dm + n]     += gelu_exact(acc[mt][nt][2] + b0);
                OUT[(size_t)tB * Dm + n + 1] += gelu_exact(acc[mt][nt][3] + b1);
            }
        }
    }
}

// =============================================================================
// Fused flash attention (tf32, R8 structure) — output written as f16.
// =============================================================================
#define QSTR 68
#define VSTR 72
#define FA_SMEM ((64 * QSTR + 2 * 64 * QSTR + 2 * 64 * VSTR) * 4)

__global__ void flash_tf32(const float* __restrict__ QKV, __half* __restrict__ O) {
    extern __shared__ unsigned sm[];
    unsigned* Qs = sm;
    unsigned* Ks = sm + 64 * QSTR;
    unsigned* Vs = sm + 64 * QSTR + 2 * 64 * QSTR;

    int bh = blockIdx.y;
    int b = bh / Hn, h = bh % Hn;
    int m0 = blockIdx.x * 64;
    int tid = threadIdx.x;
    int warp = tid >> 5, lane = tid & 31;
    int gid = lane >> 2, tg = lane & 3;
    int wm = warp * 16;

    #pragma unroll
    for (int l = 0; l < 8; l++) {
        int idx = tid + l * 128, r = idx >> 4, c4 = (idx & 15) * 4;
        cp16(&Qs[r * QSTR + c4],
             QKV + (size_t)(b * Sq + m0 + r) * 2304 + h * HDm + c4);
    }
    cp_commit(); cp_wait0(); __syncthreads();

    unsigned aq[8][4];
    #pragma unroll
    for (int k8 = 0; k8 < 8; k8++) {
        int kb = k8 * 8;
        aq[k8][0] = Qs[(wm + gid) * QSTR + kb + tg];
        aq[k8][1] = Qs[(wm + gid + 8) * QSTR + kb + tg];
        aq[k8][2] = Qs[(wm + gid) * QSTR + kb + tg + 4];
        aq[k8][3] = Qs[(wm + gid + 8) * QSTR + kb + tg + 4];
    }
    __syncthreads();

    float mr0 = -1e30f, mr1 = -1e30f, lr0 = 0.f, lr1 = 0.f;
    float o[8][4];
    #pragma unroll
    for (int nt = 0; nt < 8; nt++)
        #pragma unroll
        for (int q = 0; q < 4; q++) o[nt][q] = 0.f;

    #pragma unroll
    for (int l = 0; l < 8; l++) {
        int idx = tid + l * 128, r = idx >> 4, c4 = (idx & 15) * 4;
        cp16(&Ks[r * QSTR + c4],
             QKV + (size_t)(b * Sq + r) * 2304 + Dm + h * HDm + c4);
    }
    #pragma unroll
    for (int l = 0; l < 8; l++) {
        int idx = tid + l * 128, r = idx >> 4, c4 = (idx & 15) * 4;
        cp16(&Vs[r * VSTR + c4],
             QKV + (size_t)(b * Sq + r) * 2304 + 2 * Dm + h * HDm + c4);
    }
    cp_commit();

    for (int c = 0; c < 8; c++) {
        int buf = c & 1;
        if (c + 1 < 8) {
            int nb = buf ^ 1;
            #pragma unroll
            for (int l = 0; l < 8; l++) {
                int idx = tid + l * 128, r = idx >> 4, c4 = (idx & 15) * 4;
                cp16(&Ks[nb * 64 * QSTR + r * QSTR + c4],
                     QKV + (size_t)(b * Sq + (c + 1) * 64 + r) * 2304 + Dm + h * HDm + c4);
            }
            #pragma unroll
            for (int l = 0; l < 8; l++) {
                int idx = tid + l * 128, r = idx >> 4, c4 = (idx & 15) * 4;
                cp16(&Vs[nb * 64 * VSTR + r * VSTR + c4],
                     QKV + (size_t)(b * Sq + (c + 1) * 64 + r) * 2304 + 2 * Dm + h * HDm + c4);
            }
            cp_commit();
            cp_wait1();
        } else {
            cp_wait0();
        }
        __syncthreads();
        unsigned* Kb = Ks + buf * 64 * QSTR;
        unsigned* Vb = Vs + buf * 64 * VSTR;

        float s[8][4];
        #pragma unroll
        for (int nt = 0; nt < 8; nt++)
            #pragma unroll
            for (int q = 0; q < 4; q++) s[nt][q] = 0.f;
        #pragma unroll
        for (int k8 = 0; k8 < 8; k8++) {
            int kb = k8 * 8;
            #pragma unroll
            for (int nt = 0; nt < 8; nt++) {
                int n = nt * 8 + gid;
                unsigned b0 = Kb[n * QSTR + kb + tg];
                unsigned b1 = Kb[n * QSTR + kb + tg + 4];
                mma_tf32(s[nt], aq[k8][0], aq[k8][1], aq[k8][2], aq[k8][3], b0, b1);
            }
        }

        const float sc = 0.125f;
        float mx0 = -1e30f, mx1 = -1e30f;
        #pragma unroll
        for (int nt = 0; nt < 8; nt++) {
            s[nt][0] *= sc; s[nt][1] *= sc; s[nt][2] *= sc; s[nt][3] *= sc;
            mx0 = fmaxf(mx0, fmaxf(s[nt][0], s[nt][1]));
            mx1 = fmaxf(mx1, fmaxf(s[nt][2], s[nt][3]));
        }
        mx0 = fmaxf(mx0, __shfl_xor_sync(0xffffffffu, mx0, 1));
        mx0 = fmaxf(mx0, __shfl_xor_sync(0xffffffffu, mx0, 2));
        mx1 = fmaxf(mx1, __shfl_xor_sync(0xffffffffu, mx1, 1));
        mx1 = fmaxf(mx1, __shfl_xor_sync(0xffffffffu, mx1, 2));
        float mn0 = fmaxf(mr0, mx0), mn1 = fmaxf(mr1, mx1);
        float a0 = __expf(mr0 - mn0), a1 = __expf(mr1 - mn1);
        float sum0 = 0.f, sum1 = 0.f;
        #pragma unroll
        for (int nt = 0; nt < 8; nt++) {
            s[nt][0] = __expf(s[nt][0] - mn0);
            s[nt][1] = __expf(s[nt][1] - mn0);
            s[nt][2] = __expf(s[nt][2] - mn1);
            s[nt][3] = __expf(s[nt][3] - mn1);
            sum0 += s[nt][0] + s[nt][1];
            sum1 += s[nt][2] + s[nt][3];
        }
        sum0 += __shfl_xor_sync(0xffffffffu, sum0, 1);
        sum0 += __shfl_xor_sync(0xffffffffu, sum0, 2);
        sum1 += __shfl_xor_sync(0xffffffffu, sum1, 1);
        sum1 += __shfl_xor_sync(0xffffffffu, sum1, 2);
        lr0 = lr0 * a0 + sum0;
        lr1 = lr1 * a1 + sum1;
        mr0 = mn0; mr1 = mn1;
        #pragma unroll
        for (int nt = 0; nt < 8; nt++) {
            o[nt][0] *= a0; o[nt][1] *= a0;
            o[nt][2] *= a1; o[nt][3] *= a1;
        }

        unsigned* Ps = Qs;
        #pragma unroll
        for (int nt = 0; nt < 8; nt++) {
            int cc = nt * 8 + tg * 2;
            Ps[(wm + gid) * QSTR + cc]         = f2t(s[nt][0]);
            Ps[(wm + gid) * QSTR + cc + 1]     = f2t(s[nt][1]);
            Ps[(wm + gid + 8) * QSTR + cc]     = f2t(s[nt][2]);
            Ps[(wm + gid + 8) * QSTR + cc + 1] = f2t(s[nt][3]);
        }
        __syncwarp();

        #pragma unroll
        for (int kb = 0; kb < 64; kb += 8) {
            unsigned p0 = Ps[(wm + gid) * QSTR + kb + tg];
            unsigned p1 = Ps[(wm + gid + 8) * QSTR + kb + tg];
            unsigned p2 = Ps[(wm + gid) * QSTR + kb + tg + 4];
            unsigned p3 = Ps[(wm + gid + 8) * QSTR + kb + tg + 4];
            #pragma unroll
            for (int nt = 0; nt < 8; nt++) {
                int n = nt * 8 + gid;
                unsigned v0 = Vb[(kb + tg) * VSTR + n];
                unsigned v1 = Vb[(kb + tg + 4) * VSTR + n];
                mma_tf32(o[nt], p0, p1, p2, p3, v0, v1);
            }
        }
        __syncthreads();
    }

    float inv0 = 1.0f / lr0, inv1 = 1.0f / lr1;
    int rA = b * Sq + m0 + wm + gid, rB = rA + 8;
    #pragma unroll
    for (int nt = 0; nt < 8; nt++) {
        int cc = h * HDm + nt * 8 + tg * 2;
        *(__half2*)&O[(size_t)rA * Dm + cc] = f2h2(o[nt][0] * inv0, o[nt][1] * inv0);
        *(__half2*)&O[(size_t)rB * Dm + cc] = f2h2(o[nt][2] * inv1, o[nt][3] * inv1);
    }
}

// ---------------- router (exact fp32 logits) ----------------------------------
__global__ void route_kernel(const float* __restrict__ H2,
                             const float* __restrict__ SW,
                             const float* __restrict__ SB) {
    int warp = (blockIdx.x * blockDim.x + threadIdx.x) >> 5;
    int lane = threadIdx.x & 31;
    if (warp >= TOK) return;
    const float* hrow = H2 + (size_t)warp * Dm;
    float acc[En];
    #pragma unroll
    for (int e = 0; e < En; e++) acc[e] = 0.f;
    for (int d = lane; d < Dm; d += 32) {
        float hv = hrow[d];
        const float* w = SW + d * En;
        #pragma unroll
        for (int e = 0; e < En; e++) acc[e] += hv * w[e];
    }
    #pragma unroll
    for (int e = 0; e < En; e++)
        #pragma unroll
        for (int o = 16; o; o >>= 1)
            acc[e] += __shfl_xor_sync(0xffffffffu, acc[e], o);
    if (lane == 0) {
        float best = acc[0] + SB[0];
        int be = 0;
        #pragma unroll
        for (int e = 1; e < En; e++) {
            float v = acc[e] + SB[e];
            if (v > best) { best = v; be = e; }
        }
        g_routes[warp] = be;
        atomicAdd(&g_cnt[be], 1);
    }
}

__global__ void offsets_kernel() {
    if (threadIdx.x == 0) {
        int acc = 0;
        for (int e = 0; e < En; e++) { g_off[e] = acc; acc += g_cnt[e]; }
    }
}

__global__ void scatter_kernel() {
    int t = blockIdx.x * blockDim.x + threadIdx.x;
    if (t >= TOK) return;
    int e = g_routes[t];
    int pos = atomicAdd(&g_cur[e], 1);
    g_sorted[g_off[e] + pos] = t;
}

// ---------------- launch ------------------------------------------------------
extern "C" void kernel_launch(void* const* d_in, const int* in_sizes, int n_in,
                              void* d_out, int out_size) {
    const float* x       = (const float*)d_in[0];
    // d_in[1] = indexes_list (unused by reference math)
    const float* ln1_g   = (const float*)d_in[2];
    const float* ln1_b   = (const float*)d_in[3];
    const float* qkv_w   = (const float*)d_in[4];
    const float* proj_w  = (const float*)d_in[5];
    const float* proj_b  = (const float*)d_in[6];
    const float* ln2_g   = (const float*)d_in[7];
    const float* ln2_b   = (const float*)d_in[8];
    const float* sw_w    = (const float*)d_in[9];
    const float* sw_b    = (const float*)d_in[10];
    const float* w1      = (const float*)d_in[11];
    const float* b1      = (const float*)d_in[12];
    const float* w2      = (const float*)d_in[13];
    const float* b2      = (const float*)d_in[14];
    float* out = (float*)d_out;

    __half *gh, *go, *ghh, *gy1, *gqT, *gpT, *g1T, *g2T;
    float *gqkv, *gh2;
    cudaGetSymbolAddress((void**)&gh,   g_h);
    cudaGetSymbolAddress((void**)&gqkv, g_qkv);
    cudaGetSymbolAddress((void**)&go,   g_o);
    cudaGetSymbolAddress((void**)&gh2,  g_h2);
    cudaGetSymbolAddress((void**)&ghh,  g_hh);
    cudaGetSymbolAddress((void**)&gy1,  g_y1);
    cudaGetSymbolAddress((void**)&gqT,  g_qkvT);
    cudaGetSymbolAddress((void**)&gpT,  g_projT);
    cudaGetSymbolAddress((void**)&g1T,  g_w1T);
    cudaGetSymbolAddress((void**)&g2T,  g_w2T);

    static int smem_set = 0;
    if (!smem_set) {
        cudaFuncSetAttribute(flash_tf32, cudaFuncAttributeMaxDynamicSharedMemorySize, FA_SMEM);
        cudaFuncSetAttribute(gemm_f16,  cudaFuncAttributeMaxDynamicSharedMemorySize, GEMM_SMEM_H);
        cudaFuncSetAttribute(moe1_f16,  cudaFuncAttributeMaxDynamicSharedMemorySize, GEMM_SMEM_H);
        cudaFuncSetAttribute(moe2_f16,  cudaFuncAttributeMaxDynamicSharedMemorySize, GEMM_SMEM_H);
        smem_set = 1;
    }

    reset_kernel<<<1, 32>>>();

    // weight transposes -> f16 [n][k]
    transpose_h<<<dim3(3 * Dm / 32, Dm / 32), dim3(32, 8)>>>(qkv_w, gqT, Dm, 3 * Dm);
    transpose_h<<<dim3(Dm / 32, Dm / 32), dim3(32, 8)>>>(proj_w, gpT, Dm, Dm);
    transpose_h<<<dim3(FFd / 32, Dm / 32, En), dim3(32, 8)>>>(w1, g1T, Dm, FFd);
    transpose_h<<<dim3(Dm / 32, FFd / 32, En), dim3(32, 8)>>>(w2, g2T, FFd, Dm);

    // ln1 -> f16
    ln_kernel<<<TOK, 256>>>(x, ln1_g, ln1_b, nullptr, gh);
    // qkv = h @ qkv_w (f16 mma), C fp32 tf32-rounded (flash operand)
    gemm_f16<<<dim3(3 * Dm / 128, TOK / 128), 256, GEMM_SMEM_H>>>(
        gh, gqT, gqkv, 3 * Dm, Dm, nullptr, nullptr, 1);
    // fused attention (tf32) -> f16 output
    flash_tf32<<<dim3(Sq / 64, BHN), 128, FA_SMEM>>>(gqkv, go);
    // xmid = x + o @ proj_w + proj_b -> d_out (exact fp32)
    gemm_f16<<<dim3(Dm / 128, TOK / 128), 256, GEMM_SMEM_H>>>(
        go, gpT, out, Dm, Dm, proj_b, x, 0);
    // ln2 -> fp32 (router) + f16 (moe1 A)
    ln_kernel<<<TOK, 256>>>(out, ln2_g, ln2_b, gh2, ghh);
    // routing
    route_kernel<<<512, 256>>>(gh2, sw_w, sw_b);
    offsets_kernel<<<1, 32>>>();
    scatter_kernel<<<TOK / 256, 256>>>();
    // MoE expert GEMMs (f16 mma)
    moe1_f16<<<dim3(FFd / 128, TOK / 128, En), 256, GEMM_SMEM_H>>>(ghh, g1T, b1, gy1);
    moe2_f16<<<dim3(Dm / 128, TOK / 128, En), 256, GEMM_SMEM_H>>>(gy1, g2T, b2, out);
}

// round 15
// speedup vs baseline: 1.2901x; 1.0136x over previous
#include <cuda_runtime.h>
#include <cuda_fp16.h>
#include <stdint.h>
#include <math.h>

#define Bsz 8
#define Sq  512
#define Dm  768
#define Hn  12
#define HDm 64
#define En  8
#define FFd 3072
#define TOK 4096
#define BHN 96
#define BKh 32

// ---------------- scratch (device globals; no allocations allowed) ----------
__device__ __half g_h[TOK * Dm];             // ln1 out (f16)
__device__ float  g_qkv[TOK * 3 * Dm];       // tf32-grid fp32 (flash operand)
__device__ __half g_o[TOK * Dm];             // flash out (f16)
__device__ float  g_h2[TOK * Dm];            // ln2 out exact (router)
__device__ __half g_hh[TOK * Dm];            // ln2 out f16 (moe1 A)
__device__ __half g_y1[(size_t)TOK * FFd];   // moe hidden (f16)
__device__ __half g_qkvT[3 * Dm * Dm];
__device__ __half g_projT[Dm * Dm];
__device__ __half g_w1T[(size_t)En * FFd * Dm];
__device__ __half g_w2T[(size_t)En * Dm * FFd];
__device__ int    g_routes[TOK];
__device__ int    g_cnt[En];
__device__ int    g_off[En];
__device__ int    g_cur[En];
__device__ int    g_sorted[TOK];

// ---------------- helpers ---------------------------------------------------
__device__ __forceinline__ float gelu_exact(float x) {
    return 0.5f * x * (1.0f + erff(x * 0.70710678118654752f));
}
__device__ __forceinline__ unsigned f2t(float f) {
    unsigned u;
    asm("cvt.rna.tf32.f32 %0, %1;" : "=r"(u) : "f"(f));
    return u;
}
__device__ __forceinline__ float rtf(float f) { return __uint_as_float(f2t(f)); }

__device__ __forceinline__ void mma_tf32(float c[4],
                                         unsigned a0, unsigned a1, unsigned a2, unsigned a3,
                                         unsigned b0, unsigned b1) {
    asm volatile(
        "mma.sync.aligned.m16n8k8.row.col.f32.tf32.tf32.f32 "
        "{%0,%1,%2,%3},{%4,%5,%6,%7},{%8,%9},{%0,%1,%2,%3};"
        : "+f"(c[0]), "+f"(c[1]), "+f"(c[2]), "+f"(c[3])
        : "r"(a0), "r"(a1), "r"(a2), "r"(a3), "r"(b0), "r"(b1));
}

__device__ __forceinline__ void mma_f16(float c[4],
                                        unsigned a0, unsigned a1, unsigned a2, unsigned a3,
                                        unsigned b0, unsigned b1) {
    asm volatile(
        "mma.sync.aligned.m16n8k16.row.col.f32.f16.f16.f32 "
        "{%0,%1,%2,%3},{%4,%5,%6,%7},{%8,%9},{%0,%1,%2,%3};"
        : "+f"(c[0]), "+f"(c[1]), "+f"(c[2]), "+f"(c[3])
        : "r"(a0), "r"(a1), "r"(a2), "r"(a3), "r"(b0), "r"(b1));
}

__device__ __forceinline__ void ldsm4(unsigned& r0, unsigned& r1, unsigned& r2, unsigned& r3,
                                      unsigned addr) {
    asm volatile("ldmatrix.sync.aligned.m8n8.x4.shared.b16 {%0,%1,%2,%3}, [%4];"
        : "=r"(r0), "=r"(r1), "=r"(r2), "=r"(r3) : "r"(addr));
}
__device__ __forceinline__ void ldsm2(unsigned& r0, unsigned& r1, unsigned addr) {
    asm volatile("ldmatrix.sync.aligned.m8n8.x2.shared.b16 {%0,%1}, [%2];"
        : "=r"(r0), "=r"(r1) : "r"(addr));
}

__device__ __forceinline__ void cp16(void* d, const void* s) {
    unsigned sd = (unsigned)__cvta_generic_to_shared(d);
    asm volatile("cp.async.cg.shared.global [%0], [%1], 16;" :: "r"(sd), "l"(s));
}
__device__ __forceinline__ void cp16z(void* d, const void* s, int pred) {
    unsigned sd = (unsigned)__cvta_generic_to_shared(d);
    int sz = pred ? 16 : 0;
    asm volatile("cp.async.cg.shared.global [%0], [%1], 16, %2;" :: "r"(sd), "l"(s), "r"(sz));
}
__device__ __forceinline__ void cp_commit() { asm volatile("cp.async.commit_group;"); }
__device__ __forceinline__ void cp_wait0()  { asm volatile("cp.async.wait_group 0;"); }
__device__ __forceinline__ void cp_wait1()  { asm volatile("cp.async.wait_group 1;"); }

__device__ __forceinline__ __half2 f2h2(float a, float b) {
    return __halves2half2(__float2half_rn(a), __float2half_rn(b));
}

// ---------------- reset counters --------------------------------------------
__global__ void reset_kernel() {
    int t = threadIdx.x;
    if (t < En) { g_cnt[t] = 0; g_cur[t] = 0; }
}

// ---------------- transpose + f16 convert: Wt[n][k] = h(W[k][n]) ------------
__global__ void transpose_h(const float* __restrict__ W, __half* __restrict__ Wt,
                            int K, int N) {
    size_t eo = (size_t)blockIdx.z * K * N;
    W += eo; Wt += eo;
    __shared__ float t[32][33];
    int n0 = blockIdx.x * 32, k0 = blockIdx.y * 32;
    int tx = threadIdx.x, ty = threadIdx.y;
    #pragma unroll
    for (int l = 0; l < 4; l++)
        t[ty + l * 8][tx] = W[(size_t)(k0 + ty + l * 8) * N + n0 + tx];
    __syncthreads();
    #pragma unroll
    for (int l = 0; l < 4; l++)
        Wt[(size_t)(n0 + ty + l * 8) * K + k0 + tx] = __float2half_rn(t[tx][ty + l * 8]);
}

// ---------------- layernorm: outputs fp32 (opt) and/or f16 (opt) ------------
__global__ void ln_kernel(const float* __restrict__ X,
                          const float* __restrict__ gam,
                          const float* __restrict__ bet,
                          float* __restrict__ Yf, __half* __restrict__ Yh) {
    int row = blockIdx.x;
    int tid = threadIdx.x;
    const float* x = X + (size_t)row * Dm;
    float v0 = x[tid], v1 = x[tid + 256], v2 = x[tid + 512];

    __shared__ float red[256];
    red[tid] = v0 + v1 + v2; __syncthreads();
    #pragma unroll
    for (int st = 128; st > 0; st >>= 1) {
        if (tid < st) red[tid] += red[tid + st];
        __syncthreads();
    }
    float mu = red[0] / (float)Dm;
    __syncthreads();

    float d0 = v0 - mu, d1 = v1 - mu, d2 = v2 - mu;
    red[tid] = d0 * d0 + d1 * d1 + d2 * d2; __syncthreads();
    #pragma unroll
    for (int st = 128; st > 0; st >>= 1) {
        if (tid < st) red[tid] += red[tid + st];
        __syncthreads();
    }
    float rstd = rsqrtf(red[0] / (float)Dm + 1e-5f);

    float o0 = d0 * rstd * gam[tid]       + bet[tid];
    float o1 = d1 * rstd * gam[tid + 256] + bet[tid + 256];
    float o2 = d2 * rstd * gam[tid + 512] + bet[tid + 512];
    if (Yf) {
        float* y = Yf + (size_t)row * Dm;
        y[tid] = o0; y[tid + 256] = o1; y[tid + 512] = o2;
    }
    if (Yh) {
        __half* y = Yh + (size_t)row * Dm;
        y[tid]       = __float2half_rn(o0);
        y[tid + 256] = __float2half_rn(o1);
        y[tid + 512] = __float2half_rn(o2);
    }
}

// =============================================================================
// f16 GEMM: BM=128, BN=128, BK=32, 3-stage cp.async ring, 256 thr = 8 warps
// (2x4), warp tile 64x32 via m16n8k16, ldmatrix fragment loads.
// smem rows: 16 half2-words padded to 20 (80B; 16B-aligned, conflict-free).
// =============================================================================
#define HSTR 20
#define HS_SZ (128 * HSTR)
#define GEMM_SMEM_H (2 * 3 * HS_SZ * 4)

__device__ __forceinline__ void h_load(unsigned* As, unsigned* Bs, int st, int gk,
                                       const __half* Arow, int okA,
                                       const __half* Brow, int lr, int lw) {
    cp16z(&As[st * HS_SZ + lr * HSTR + lw],     Arow + gk + lw * 2,     okA);
    cp16z(&As[st * HS_SZ + lr * HSTR + lw + 4], Arow + gk + lw * 2 + 8, okA);
    cp16(&Bs[st * HS_SZ + lr * HSTR + lw],      Brow + gk + lw * 2);
    cp16(&Bs[st * HS_SZ + lr * HSTR + lw + 4],  Brow + gk + lw * 2 + 8);
    cp_commit();
}

// ldmatrix-based stage compute. asu/bsu: u32 shared addrs of this stage's
// A/B base. lane-mapped addresses per the m8n8 tile contract.
__device__ __forceinline__ void h_mma_stage(unsigned asu, unsigned bsu,
                                            float acc[4][4][4],
                                            int wm, int wn, int lane) {
    unsigned aAddr = asu + (unsigned)((wm + (lane & 15)) * HSTR) * 4u
                   + (unsigned)(lane >> 4) * 16u;
    unsigned bAddr = bsu + (unsigned)((wn + (lane & 7)) * HSTR) * 4u
                   + (unsigned)((lane >> 3) & 1) * 16u;
    #pragma unroll
    for (int ks = 0; ks < 2; ks++) {
        unsigned koff = (unsigned)ks * 32u;
        unsigned af[4][4], bf[4][2];
        #pragma unroll
        for (int mt = 0; mt < 4; mt++)
            ldsm4(af[mt][0], af[mt][1], af[mt][2], af[mt][3],
                  aAddr + (unsigned)(mt * 16 * HSTR) * 4u + koff);
        #pragma unroll
        for (int nt = 0; nt < 4; nt++)
            ldsm2(bf[nt][0], bf[nt][1],
                  bAddr + (unsigned)(nt * 8 * HSTR) * 4u + koff);
        #pragma unroll
        for (int mt = 0; mt < 4; mt++)
            #pragma unroll
            for (int nt = 0; nt < 4; nt++)
                mma_f16(acc[mt][nt], af[mt][0], af[mt][1], af[mt][2], af[mt][3],
                        bf[nt][0], bf[nt][1]);
    }
}

// ---- dense f16 GEMM: C(fp32) = A @ Wt^T (+bias)(+resid)(tf32-round) ---------
__global__ void __launch_bounds__(256)
gemm_f16(const __half* __restrict__ A, const __half* __restrict__ Wt,
         float* __restrict__ C, int N, int K,
         const float* __restrict__ bias, const float* __restrict__ resid, int rnd) {
    extern __shared__ unsigned smg[];
    unsigned* As = smg;
    unsigned* Bs = smg + 3 * HS_SZ;
    unsigned asu = (unsigned)__cvta_generic_to_shared(As);
    unsigned bsu = (unsigned)__cvta_generic_to_shared(Bs);
    int tid = threadIdx.x, warp = tid >> 5, lane = tid & 31;
    int gid = lane >> 2, tg = lane & 3;
    int wm = (warp >> 2) * 64, wn = (warp & 3) * 32;
    int m0 = blockIdx.y * 128, n0 = blockIdx.x * 128;

    float acc[4][4][4];
    #pragma unroll
    for (int i = 0; i < 4; i++)
        #pragma unroll
        for (int j = 0; j < 4; j++)
            #pragma unroll
            for (int q = 0; q < 4; q++) acc[i][j][q] = 0.f;

    int lr = tid >> 1, lw = (tid & 1) * 8;
    const __half* Arow = A + (size_t)(m0 + lr) * K;
    const __half* Brow = Wt + (size_t)(n0 + lr) * K;

    h_load(As, Bs, 0, 0,   Arow, 1, Brow, lr, lw);
    h_load(As, Bs, 1, BKh, Arow, 1, Brow, lr, lw);

    int nk = K / BKh;
    for (int kt = 0; kt < nk; kt++) {
        int s = kt % 3;
        cp_wait1(); __syncthreads();
        if (kt + 2 < nk) {
            h_load(As, Bs, (kt + 2) % 3, (kt + 2) * BKh, Arow, 1, Brow, lr, lw);
        } else {
            cp_commit();
        }
        h_mma_stage(asu + s * HS_SZ * 4, bsu + s * HS_SZ * 4, acc, wm, wn, lane);
    }

    #pragma unroll
    for (int mt = 0; mt < 4; mt++) {
        int mA = m0 + wm + mt * 16 + gid, mB = mA + 8;
        #pragma unroll
        for (int nt = 0; nt < 4; nt++) {
            int n = n0 + wn + nt * 8 + tg * 2;
            float v0 = acc[mt][nt][0], v1 = acc[mt][nt][1];
            float v2 = acc[mt][nt][2], v3 = acc[mt][nt][3];
            if (bias) {
                float b0 = bias[n], b1 = bias[n + 1];
                v0 += b0; v1 += b1; v2 += b0; v3 += b1;
            }
            if (resid) {
                v0 += resid[(size_t)mA * N + n];
                v1 += resid[(size_t)mA * N + n + 1];
                v2 += resid[(size_t)mB * N + n];
                v3 += resid[(size_t)mB * N + n + 1];
            }
            if (rnd) { v0 = rtf(v0); v1 = rtf(v1); v2 = rtf(v2); v3 = rtf(v3); }
            C[(size_t)mA * N + n]     = v0;
            C[(size_t)mA * N + n + 1] = v1;
            C[(size_t)mB * N + n]     = v2;
            C[(size_t)mB * N + n + 1] = v3;
        }
    }
}

// ---- MoE GEMM1: Y1(f16) = gelu(gather(Hh) @ w1T^T + b1) ---------------------
__global__ void __launch_bounds__(256)
moe1_f16(const __half* __restrict__ Hh, const __half* __restrict__ W1T,
         const float* __restrict__ B1, __half* __restrict__ Y1) {
    int e = blockIdx.z;
    int cnt = g_cnt[e];
    int m0 = blockIdx.y * 128;
    if (m0 >= cnt) return;
    int off = g_off[e];

    extern __shared__ unsigned smg[];
    unsigned* As = smg;
    unsigned* Bs = smg + 3 * HS_SZ;
    unsigned asu = (unsigned)__cvta_generic_to_shared(As);
    unsigned bsu = (unsigned)__cvta_generic_to_shared(Bs);
    __shared__ int toks[128];
    int tid = threadIdx.x, warp = tid >> 5, lane = tid & 31;
    int gid = lane >> 2, tg = lane & 3;
    int wm = (warp >> 2) * 64, wn = (warp & 3) * 32;
    if (tid < 128) {
        int m = m0 + tid;
        toks[tid] = (m < cnt) ? g_sorted[off + m] : -1;
    }
    __syncthreads();

    float acc[4][4][4];
    #pragma unroll
    for (int i = 0; i < 4; i++)
        #pragma unroll
        for (int j = 0; j < 4; j++)
            #pragma unroll
            for (int q = 0; q < 4; q++) acc[i][j][q] = 0.f;

    int n0 = blockIdx.x * 128;
    int lr = tid >> 1, lw = (tid & 1) * 8;
    int tok = toks[lr];
    const __half* Arow = Hh + (size_t)(tok >= 0 ? tok : 0) * Dm;
    const __half* Brow = W1T + (size_t)e * FFd * Dm + (size_t)(n0 + lr) * Dm;
    int okA = tok >= 0;

    h_load(As, Bs, 0, 0,   Arow, okA, Brow, lr, lw);
    h_load(As, Bs, 1, BKh, Arow, okA, Brow, lr, lw);

    int nk = Dm / BKh;
    for (int kt = 0; kt < nk; kt++) {
        int s = kt % 3;
        cp_wait1(); __syncthreads();
        if (kt + 2 < nk) {
            h_load(As, Bs, (kt + 2) % 3, (kt + 2) * BKh, Arow, okA, Brow, lr, lw);
        } else {
            cp_commit();
        }
        h_mma_stage(asu + s * HS_SZ * 4, bsu + s * HS_SZ * 4, acc, wm, wn, lane);
    }

    #pragma unroll
    for (int mt = 0; mt < 4; mt++) {
        int gmA = m0 + wm + mt * 16 + gid, gmB = gmA + 8;
        #pragma unroll
        for (int nt = 0; nt < 4; nt++) {
            int n = n0 + wn + nt * 8 + tg * 2;
            float b0 = B1[e * FFd + n], b1 = B1[e * FFd + n + 1];
            if (gmA < cnt) {
                float v0 = gelu_exact(acc[mt][nt][0] + b0);
                float v1 = gelu_exact(acc[mt][nt][1] + b1);
                *(__half2*)&Y1[(size_t)(off + gmA) * FFd + n] = f2h2(v0, v1);
            }
            if (gmB < cnt) {
                float v2 = gelu_exact(acc[mt][nt][2] + b0);
                float v3 = gelu_exact(acc[mt][nt][3] + b1);
                *(__half2*)&Y1[(size_t)(off + gmB) * FFd + n] = f2h2(v2, v3);
            }
        }
    }
}

// ---- MoE GEMM2: OUT(fp32)[tok] += gelu(Y1 @ w2T^T + b2) ---------------------
__global__ void __launch_bounds__(256)
moe2_f16(const __half* __restrict__ Y1, const __half* __restrict__ W2T,
         const float* __restrict__ B2, float* __restrict__ OUT) {
    int e = blockIdx.z;
    int cnt = g_cnt[e];
    int m0 = blockIdx.y * 128;
    if (m0 >= cnt) return;
    int off = g_off[e];

    extern __shared__ unsigned smg[];
    unsigned* As = smg;
    unsigned* Bs = smg + 3 * HS_SZ;
    unsigned asu = (unsigned)__cvta_generic_to_shared(As);
    unsigned bsu = (unsigned)__cvta_generic_to_shared(Bs);
    __shared__ int toks[128];
    int tid = threadIdx.x, warp = tid >> 5, lane = tid & 31;
    int gid = lane >> 2, tg = lane & 3;
    int wm = (warp >> 2) * 64, wn = (warp & 3) * 32;
    if (tid < 128) {
        int m = m0 + tid;
        toks[tid] = (m < cnt) ? g_sorted[off + m] : -1;
    }
    __syncthreads();

    float acc[4][4][4];
    #pragma unroll
    for (int i = 0; i < 4; i++)
        #pragma unroll
        for (int j = 0; j < 4; j++)
            #pragma unroll
            for (int q = 0; q < 4; q++) acc[i][j][q] = 0.f;

    int n0 = blockIdx.x * 128;
    int lr = tid >> 1, lw = (tid & 1) * 8;
    int okA = (m0 + lr) < cnt;
    const __half* Arow = Y1 + (size_t)(off + (okA ? m0 + lr : 0)) * FFd;
    const __half* Brow = W2T + (size_t)e * Dm * FFd + (size_t)(n0 + lr) * FFd;

    h_load(As, Bs, 0, 0,   Arow, okA, Brow, lr, lw);
    h_load(As, Bs, 1, BKh, Arow, okA, Brow, lr, lw);

    int nk = FFd / BKh;
    for (int kt = 0; kt < nk; kt++) {
        int s = kt % 3;
        cp_wait1(); __syncthreads();
        if (kt + 2 < nk) {
            h_load(As, Bs, (kt + 2) % 3, (kt + 2) * BKh, Arow, okA, Brow, lr, lw);
        } else {
            cp_commit();
        }
        h_mma_stage(asu + s * HS_SZ * 4, bsu + s * HS_SZ * 4, acc, wm, wn, lane);
    }

    #pragma unroll
    for (int mt = 0; mt < 4; mt++) {
        int lmA = wm + mt * 16 + gid;
        int gmA = m0 + lmA, gmB = gmA + 8;
        int tA = toks[lmA], tB = toks[lmA + 8];
        #pragma unroll
        for (int nt = 0; nt < 4; nt++) {
            int n = n0 + wn + nt * 8 + tg * 2;
            float b0 = B2[e * Dm + n], b1 = B2[e * Dm + n + 1];
            if (gmA < cnt) {
                OUT[(size_t)tA * Dm + n]     += gelu_exact(acc[mt][nt][0] + b0);
                OUT[(size_t)tA * Dm + n + 1] += gelu_exact(acc[mt][nt][1] + b1);
            }
            if (gmB < cnt) {
                OUT[(size_t)tB * Dm + n]     += gelu_exact(acc[mt][nt][2] + b0);
                OUT[(size_t)tB * Dm + n + 1] += gelu_exact(acc[mt][nt][3] + b1);
            }
        }
    }
}

// =============================================================================
// Fused flash attention (tf32, R8 structure) — output written as f16.
// =============================================================================
#define QSTR 68
#define VSTR 72
#define FA_SMEM ((64 * QSTR + 2 * 64 * QSTR + 2 * 64 * VSTR) * 4)

__global__ void flash_tf32(const float* __restrict__ QKV, __half* __restrict__ O) {
    extern __shared__ unsigned sm[];
    unsigned* Qs = sm;
    unsigned* Ks = sm + 64 * QSTR;
    unsigned* Vs = sm + 64 * QSTR + 2 * 64 * QSTR;

    int bh = blockIdx.y;
    int b = bh / Hn, h = bh % Hn;
    int m0 = blockIdx.x * 64;
    int tid = threadIdx.x;
    int warp = tid >> 5, lane = tid & 31;
    int gid = lane >> 2, tg = lane & 3;
    int wm = warp * 16;

    #pragma unroll
    for (int l = 0; l < 8; l++) {
        int idx = tid + l * 128, r = idx >> 4, c4 = (idx & 15) * 4;
        cp16(&Qs[r * QSTR + c4],
             QKV + (size_t)(b * Sq + m0 + r) * 2304 + h * HDm + c4);
    }
    cp_commit(); cp_wait0(); __syncthreads();

    unsigned aq[8][4];
    #pragma unroll
    for (int k8 = 0; k8 < 8; k8++) {
        int kb = k8 * 8;
        aq[k8][0] = Qs[(wm + gid) * QSTR + kb + tg];
        aq[k8][1] = Qs[(wm + gid + 8) * QSTR + kb + tg];
        aq[k8][2] = Qs[(wm + gid) * QSTR + kb + tg + 4];
        aq[k8][3] = Qs[(wm + gid + 8) * QSTR + kb + tg + 4];
    }
    __syncthreads();

    float mr0 = -1e30f, mr1 = -1e30f, lr0 = 0.f, lr1 = 0.f;
    float o[8][4];
    #pragma unroll
    for (int nt = 0; nt < 8; nt++)
        #pragma unroll
        for (int q = 0; q < 4; q++) o[nt][q] = 0.f;

    #pragma unroll
    for (int l = 0; l < 8; l++) {
        int idx = tid + l * 128, r = idx >> 4, c4 = (idx & 15) * 4;
        cp16(&Ks[r * QSTR + c4],
             QKV + (size_t)(b * Sq + r) * 2304 + Dm + h * HDm + c4);
    }
    #pragma unroll
    for (int l = 0; l < 8; l++) {
        int idx = tid + l * 128, r = idx >> 4, c4 = (idx & 15) * 4;
        cp16(&Vs[r * VSTR + c4],
             QKV + (size_t)(b * Sq + r) * 2304 + 2 * Dm + h * HDm + c4);
    }
    cp_commit();

    for (int c = 0; c < 8; c++) {
        int buf = c & 1;
        if (c + 1 < 8) {
            int nb = buf ^ 1;
            #pragma unroll
            for (int l = 0; l < 8; l++) {
                int idx = tid + l * 128, r = idx >> 4, c4 = (idx & 15) * 4;
                cp16(&Ks[nb * 64 * QSTR + r * QSTR + c4],
                     QKV + (size_t)(b * Sq + (c + 1) * 64 + r) * 2304 + Dm + h * HDm + c4);
            }
            #pragma unroll
            for (int l = 0; l < 8; l++) {
                int idx = tid + l * 128, r = idx >> 4, c4 = (idx & 15) * 4;
                cp16(&Vs[nb * 64 * VSTR + r * VSTR + c4],
                     QKV + (size_t)(b * Sq + (c + 1) * 64 + r) * 2304 + 2 * Dm + h * HDm + c4);
            }
            cp_commit();
            cp_wait1();
        } else {
            cp_wait0();
        }
        __syncthreads();
        unsigned* Kb = Ks + buf * 64 * QSTR;
        unsigned* Vb = Vs + buf * 64 * VSTR;

        float s[8][4];
        #pragma unroll
        for (int nt = 0; nt < 8; nt++)
            #pragma unroll
            for (int q = 0; q < 4; q++) s[nt][q] = 0.f;
        #pragma unroll
        for (int k8 = 0; k8 < 8; k8++) {
            int kb = k8 * 8;
            #pragma unroll
            for (int nt = 0; nt < 8; nt++) {
                int n = nt * 8 + gid;
                unsigned b0 = Kb[n * QSTR + kb + tg];
                unsigned b1 = Kb[n * QSTR + kb + tg + 4];
                mma_tf32(s[nt], aq[k8][0], aq[k8][1], aq[k8][2], aq[k8][3], b0, b1);
            }
        }

        const float sc = 0.125f;
        float mx0 = -1e30f, mx1 = -1e30f;
        #pragma unroll
        for (int nt = 0; nt < 8; nt++) {
            s[nt][0] *= sc; s[nt][1] *= sc; s[nt][2] *= sc; s[nt][3] *= sc;
            mx0 = fmaxf(mx0, fmaxf(s[nt][0], s[nt][1]));
            mx1 = fmaxf(mx1, fmaxf(s[nt][2], s[nt][3]));
        }
        mx0 = fmaxf(mx0, __shfl_xor_sync(0xffffffffu, mx0, 1));
        mx0 = fmaxf(mx0, __shfl_xor_sync(0xffffffffu, mx0, 2));
        mx1 = fmaxf(mx1, __shfl_xor_sync(0xffffffffu, mx1, 1));
        mx1 = fmaxf(mx1, __shfl_xor_sync(0xffffffffu, mx1, 2));
        float mn0 = fmaxf(mr0, mx0), mn1 = fmaxf(mr1, mx1);
        float a0 = __expf(mr0 - mn0), a1 = __expf(mr1 - mn1);
        float sum0 = 0.f, sum1 = 0.f;
        #pragma unroll
        for (int nt = 0; nt < 8; nt++) {
            s[nt][0] = __expf(s[nt][0] - mn0);
            s[nt][1] = __expf(s[nt][1] - mn0);
            s[nt][2] = __expf(s[nt][2] - mn1);
            s[nt][3] = __expf(s[nt][3] - mn1);
            sum0 += s[nt][0] + s[nt][1];
            sum1 += s[nt][2] + s[nt][3];
        }
        sum0 += __shfl_xor_sync(0xffffffffu, sum0, 1);
        sum0 += __shfl_xor_sync(0xffffffffu, sum0, 2);
        sum1 += __shfl_xor_sync(0xffffffffu, sum1, 1);
        sum1 += __shfl_xor_sync(0xffffffffu, sum1, 2);
        lr0 = lr0 * a0 + sum0;
        lr1 = lr1 * a1 + sum1;
        mr0 = mn0; mr1 = mn1;
        #pragma unroll
        for (int nt = 0; nt < 8; nt++) {
            o[nt][0] *= a0; o[nt][1] *= a0;
            o[nt][2] *= a1; o[nt][3] *= a1;
        }

        unsigned* Ps = Qs;
        #pragma unroll
        for (int nt = 0; nt < 8; nt++) {
            int cc = nt * 8 + tg * 2;
            Ps[(wm + gid) * QSTR + cc]         = f2t(s[nt][0]);
            Ps[(wm + gid) * QSTR + cc + 1]     = f2t(s[nt][1]);
            Ps[(wm + gid + 8) * QSTR + cc]     = f2t(s[nt][2]);
            Ps[(wm + gid + 8) * QSTR + cc + 1] = f2t(s[nt][3]);
        }
        __syncwarp();

        #pragma unroll
        for (int kb = 0; kb < 64; kb += 8) {
            unsigned p0 = Ps[(wm + gid) * QSTR + kb + tg];
            unsigned p1 = Ps[(wm + gid + 8) * QSTR + kb + tg];
            unsigned p2 = Ps[(wm + gid) * QSTR + kb + tg + 4];
            unsigned p3 = Ps[(wm + gid + 8) * QSTR + kb + tg + 4];
            #pragma unroll
            for (int nt = 0; nt < 8; nt++) {
                int n = nt * 8 + gid;
                unsigned v0 = Vb[(kb + tg) * VSTR + n];
                unsigned v1 = Vb[(kb + tg + 4) * VSTR + n];
                mma_tf32(o[nt], p0, p1, p2, p3, v0, v1);
            }
        }
        __syncthreads();
    }

    float inv0 = 1.0f / lr0, inv1 = 1.0f / lr1;
    int rA = b * Sq + m0 + wm + gid, rB = rA + 8;
    #pragma unroll
    for (int nt = 0; nt < 8; nt++) {
        int cc = h * HDm + nt * 8 + tg * 2;
        *(__half2*)&O[(size_t)rA * Dm + cc] = f2h2(o[nt][0] * inv0, o[nt][1] * inv0);
        *(__half2*)&O[(size_t)rB * Dm + cc] = f2h2(o[nt][2] * inv1, o[nt][3] * inv1);
    }
}

// ---------------- router (exact fp32 logits) ----------------------------------
__global__ void route_kernel(const float* __restrict__ H2,
                             const float* __restrict__ SW,
                             const float* __restrict__ SB) {
    int warp = (blockIdx.x * blockDim.x + threadIdx.x) >> 5;
    int lane = threadIdx.x & 31;
    if (warp >= TOK) return;
    const float* hrow = H2 + (size_t)warp * Dm;
    float acc[En];
    #pragma unroll
    for (int e = 0; e < En; e++) acc[e] = 0.f;
    for (int d = lane; d < Dm; d += 32) {
        float hv = hrow[d];
        const float* w = SW + d * En;
        #pragma unroll
        for (int e = 0; e < En; e++) acc[e] += hv * w[e];
    }
    #pragma unroll
    for (int e = 0; e < En; e++)
        #pragma unroll
        for (int o = 16; o; o >>= 1)
            acc[e] += __shfl_xor_sync(0xffffffffu, acc[e], o);
    if (lane == 0) {
        float best = acc[0] + SB[0];
        int be = 0;
        #pragma unroll
        for (int e = 1; e < En; e++) {
            float v = acc[e] + SB[e];
            if (v > best) { best = v; be = e; }
        }
        g_routes[warp] = be;
        atomicAdd(&g_cnt[be], 1);
    }
}

__global__ void offsets_kernel() {
    if (threadIdx.x == 0) {
        int acc = 0;
        for (int e = 0; e < En; e++) { g_off[e] = acc; acc += g_cnt[e]; }
    }
}

__global__ void scatter_kernel() {
    int t = blockIdx.x * blockDim.x + threadIdx.x;
    if (t >= TOK) return;
    int e = g_routes[t];
    int pos = atomicAdd(&g_cur[e], 1);
    g_sorted[g_off[e] + pos] = t;
}

// ---------------- launch ------------------------------------------------------
extern "C" void kernel_launch(void* const* d_in, const int* in_sizes, int n_in,
                              void* d_out, int out_size) {
    const float* x       = (const float*)d_in[0];
    // d_in[1] = indexes_list (unused by reference math)
    const float* ln1_g   = (const float*)d_in[2];
    const float* ln1_b   = (const float*)d_in[3];
    const float* qkv_w   = (const float*)d_in[4];
    const float* proj_w  = (const float*)d_in[5];
    const float* proj_b  = (const float*)d_in[6];
    const float* ln2_g   = (const float*)d_in[7];
    const float* ln2_b   = (const float*)d_in[8];
    const float* sw_w    = (const float*)d_in[9];
    const float* sw_b    = (const float*)d_in[10];
    const float* w1      = (const float*)d_in[11];
    const float* b1      = (const float*)d_in[12];
    const float* w2      = (const float*)d_in[13];
    const float* b2      = (const float*)d_in[14];
    float* out = (float*)d_out;

    __half *gh, *go, *ghh, *gy1, *gqT, *gpT, *g1T, *g2T;
    float *gqkv, *gh2;
    cudaGetSymbolAddress((void**)&gh,   g_h);
    cudaGetSymbolAddress((void**)&gqkv, g_qkv);
    cudaGetSymbolAddress((void**)&go,   g_o);
    cudaGetSymbolAddress((void**)&gh2,  g_h2);
    cudaGetSymbolAddress((void**)&ghh,  g_hh);
    cudaGetSymbolAddress((void**)&gy1,  g_y1);
    cudaGetSymbolAddress((void**)&gqT,  g_qkvT);
    cudaGetSymbolAddress((void**)&gpT,  g_projT);
    cudaGetSymbolAddress((void**)&g1T,  g_w1T);
    cudaGetSymbolAddress((void**)&g2T,  g_w2T);

    static int smem_set = 0;
    if (!smem_set) {
        cudaFuncSetAttribute(flash_tf32, cudaFuncAttributeMaxDynamicSharedMemorySize, FA_SMEM);
        cudaFuncSetAttribute(gemm_f16,  cudaFuncAttributeMaxDynamicSharedMemorySize, GEMM_SMEM_H);
        cudaFuncSetAttribute(moe1_f16,  cudaFuncAttributeMaxDynamicSharedMemorySize, GEMM_SMEM_H);
        cudaFuncSetAttribute(moe2_f16,  cudaFuncAttributeMaxDynamicSharedMemorySize, GEMM_SMEM_H);
        smem_set = 1;
    }

    reset_kernel<<<1, 32>>>();

    // weight transposes -> f16 [n][k]
    transpose_h<<<dim3(3 * Dm / 32, Dm / 32), dim3(32, 8)>>>(qkv_w, gqT, Dm, 3 * Dm);
    transpose_h<<<dim3(Dm / 32, Dm / 32), dim3(32, 8)>>>(proj_w, gpT, Dm, Dm);
    transpose_h<<<dim3(FFd / 32, Dm / 32, En), dim3(32, 8)>>>(w1, g1T, Dm, FFd);
    transpose_h<<<dim3(Dm / 32, FFd / 32, En), dim3(32, 8)>>>(w2, g2T, FFd, Dm);

    // ln1 -> f16
    ln_kernel<<<TOK, 256>>>(x, ln1_g, ln1_b, nullptr, gh);
    // qkv = h @ qkv_w (f16 mma), C fp32 tf32-rounded (flash operand)
    gemm_f16<<<dim3(3 * Dm / 128, TOK / 128), 256, GEMM_SMEM_H>>>(
        gh, gqT, gqkv, 3 * Dm, Dm, nullptr, nullptr, 1);
    // fused attention (tf32) -> f16 output
    flash_tf32<<<dim3(Sq / 64, BHN), 128, FA_SMEM>>>(gqkv, go);
    // xmid = x + o @ proj_w + proj_b -> d_out (exact fp32)
    gemm_f16<<<dim3(Dm / 128, TOK / 128), 256, GEMM_SMEM_H>>>(
        go, gpT, out, Dm, Dm, proj_b, x, 0);
    // ln2 -> fp32 (router) + f16 (moe1 A)
    ln_kernel<<<TOK, 256>>>(out, ln2_g, ln2_b, gh2, ghh);
    // routing
    route_kernel<<<512, 256>>>(gh2, sw_w, sw_b);
    offsets_kernel<<<1, 32>>>();
    scatter_kernel<<<TOK / 256, 256>>>();
    // MoE expert GEMMs (f16 mma)
    moe1_f16<<<dim3(FFd / 128, TOK / 128, En), 256, GEMM_SMEM_H>>>(ghh, g1T, b1, gy1);
    moe2_f16<<<dim3(Dm / 128, TOK / 128, En), 256, GEMM_SMEM_H>>>(gy1, g2T, b2, out);
}

// round 16
// speedup vs baseline: 1.3871x; 1.0752x over previous
#include <cuda_runtime.h>
#include <cuda_fp16.h>
#include <stdint.h>
#include <math.h>

#define Bsz 8
#define Sq  512
#define Dm  768
#define Hn  12
#define HDm 64
#define En  8
#define FFd 3072
#define TOK 4096
#define BHN 96
#define BKh 32

// ---------------- scratch (device globals; no allocations allowed) ----------
__device__ __half g_h[TOK * Dm];             // ln1 out (f16)
__device__ __half g_qkv[TOK * 3 * Dm];       // qkv (f16)
__device__ __half g_o[TOK * Dm];             // flash out (f16)
__device__ float  g_h2[TOK * Dm];            // ln2 out exact (router)
__device__ __half g_hh[TOK * Dm];            // ln2 out f16 (moe1 A)
__device__ __half g_y1[(size_t)TOK * FFd];   // moe hidden (f16)
__device__ __half g_qkvT[3 * Dm * Dm];
__device__ __half g_projT[Dm * Dm];
__device__ __half g_w1T[(size_t)En * FFd * Dm];
__device__ __half g_w2T[(size_t)En * Dm * FFd];
__device__ int    g_routes[TOK];
__device__ int    g_cnt[En];
__device__ int    g_off[En];
__device__ int    g_cur[En];
__device__ int    g_sorted[TOK];

// ---------------- helpers ---------------------------------------------------
__device__ __forceinline__ float gelu_exact(float x) {
    return 0.5f * x * (1.0f + erff(x * 0.70710678118654752f));
}
__device__ __forceinline__ void mma_f16(float c[4],
                                        unsigned a0, unsigned a1, unsigned a2, unsigned a3,
                                        unsigned b0, unsigned b1) {
    asm volatile(
        "mma.sync.aligned.m16n8k16.row.col.f32.f16.f16.f32 "
        "{%0,%1,%2,%3},{%4,%5,%6,%7},{%8,%9},{%0,%1,%2,%3};"
        : "+f"(c[0]), "+f"(c[1]), "+f"(c[2]), "+f"(c[3])
        : "r"(a0), "r"(a1), "r"(a2), "r"(a3), "r"(b0), "r"(b1));
}
__device__ __forceinline__ void ldsm4(unsigned& r0, unsigned& r1, unsigned& r2, unsigned& r3,
                                      unsigned addr) {
    asm volatile("ldmatrix.sync.aligned.m8n8.x4.shared.b16 {%0,%1,%2,%3}, [%4];"
        : "=r"(r0), "=r"(r1), "=r"(r2), "=r"(r3) : "r"(addr));
}
__device__ __forceinline__ void ldsm2(unsigned& r0, unsigned& r1, unsigned addr) {
    asm volatile("ldmatrix.sync.aligned.m8n8.x2.shared.b16 {%0,%1}, [%2];"
        : "=r"(r0), "=r"(r1) : "r"(addr));
}
__device__ __forceinline__ void ldsm2t(unsigned& r0, unsigned& r1, unsigned addr) {
    asm volatile("ldmatrix.sync.aligned.m8n8.x2.trans.shared.b16 {%0,%1}, [%2];"
        : "=r"(r0), "=r"(r1) : "r"(addr));
}

__device__ __forceinline__ void cp16(void* d, const void* s) {
    unsigned sd = (unsigned)__cvta_generic_to_shared(d);
    asm volatile("cp.async.cg.shared.global [%0], [%1], 16;" :: "r"(sd), "l"(s));
}
__device__ __forceinline__ void cp16z(void* d, const void* s, int pred) {
    unsigned sd = (unsigned)__cvta_generic_to_shared(d);
    int sz = pred ? 16 : 0;
    asm volatile("cp.async.cg.shared.global [%0], [%1], 16, %2;" :: "r"(sd), "l"(s), "r"(sz));
}
__device__ __forceinline__ void cp_commit() { asm volatile("cp.async.commit_group;"); }
__device__ __forceinline__ void cp_wait0()  { asm volatile("cp.async.wait_group 0;"); }
__device__ __forceinline__ void cp_wait1()  { asm volatile("cp.async.wait_group 1;"); }

__device__ __forceinline__ __half2 f2h2(float a, float b) {
    return __halves2half2(__float2half_rn(a), __float2half_rn(b));
}

// ---------------- reset counters --------------------------------------------
__global__ void reset_kernel() {
    int t = threadIdx.x;
    if (t < En) { g_cnt[t] = 0; g_cur[t] = 0; }
}

// ---------------- transpose + f16 convert: Wt[n][k] = h(W[k][n]) ------------
__global__ void transpose_h(const float* __restrict__ W, __half* __restrict__ Wt,
                            int K, int N) {
    size_t eo = (size_t)blockIdx.z * K * N;
    W += eo; Wt += eo;
    __shared__ float t[32][33];
    int n0 = blockIdx.x * 32, k0 = blockIdx.y * 32;
    int tx = threadIdx.x, ty = threadIdx.y;
    #pragma unroll
    for (int l = 0; l < 4; l++)
        t[ty + l * 8][tx] = W[(size_t)(k0 + ty + l * 8) * N + n0 + tx];
    __syncthreads();
    #pragma unroll
    for (int l = 0; l < 4; l++)
        Wt[(size_t)(n0 + ty + l * 8) * K + k0 + tx] = __float2half_rn(t[tx][ty + l * 8]);
}

// ---------------- layernorm: outputs fp32 (opt) and/or f16 (opt) ------------
__global__ void ln_kernel(const float* __restrict__ X,
                          const float* __restrict__ gam,
                          const float* __restrict__ bet,
                          float* __restrict__ Yf, __half* __restrict__ Yh) {
    int row = blockIdx.x;
    int tid = threadIdx.x;
    const float* x = X + (size_t)row * Dm;
    float v0 = x[tid], v1 = x[tid + 256], v2 = x[tid + 512];

    __shared__ float red[256];
    red[tid] = v0 + v1 + v2; __syncthreads();
    #pragma unroll
    for (int st = 128; st > 0; st >>= 1) {
        if (tid < st) red[tid] += red[tid + st];
        __syncthreads();
    }
    float mu = red[0] / (float)Dm;
    __syncthreads();

    float d0 = v0 - mu, d1 = v1 - mu, d2 = v2 - mu;
    red[tid] = d0 * d0 + d1 * d1 + d2 * d2; __syncthreads();
    #pragma unroll
    for (int st = 128; st > 0; st >>= 1) {
        if (tid < st) red[tid] += red[tid + st];
        __syncthreads();
    }
    float rstd = rsqrtf(red[0] / (float)Dm + 1e-5f);

    float o0 = d0 * rstd * gam[tid]       + bet[tid];
    float o1 = d1 * rstd * gam[tid + 256] + bet[tid + 256];
    float o2 = d2 * rstd * gam[tid + 512] + bet[tid + 512];
    if (Yf) {
        float* y = Yf + (size_t)row * Dm;
        y[tid] = o0; y[tid + 256] = o1; y[tid + 512] = o2;
    }
    if (Yh) {
        __half* y = Yh + (size_t)row * Dm;
        y[tid]       = __float2half_rn(o0);
        y[tid + 256] = __float2half_rn(o1);
        y[tid + 512] = __float2half_rn(o2);
    }
}

// =============================================================================
// f16 GEMM (R15 structure, ldmatrix): BM=128, BN=128, BK=32, 3-stage ring.
// C output either fp32 (Cf) or f16 (Ch).
// =============================================================================
#define HSTR 20
#define HS_SZ (128 * HSTR)
#define GEMM_SMEM_H (2 * 3 * HS_SZ * 4)

__device__ __forceinline__ void h_load(unsigned* As, unsigned* Bs, int st, int gk,
                                       const __half* Arow, int okA,
                                       const __half* Brow, int lr, int lw) {
    cp16z(&As[st * HS_SZ + lr * HSTR + lw],     Arow + gk + lw * 2,     okA);
    cp16z(&As[st * HS_SZ + lr * HSTR + lw + 4], Arow + gk + lw * 2 + 8, okA);
    cp16(&Bs[st * HS_SZ + lr * HSTR + lw],      Brow + gk + lw * 2);
    cp16(&Bs[st * HS_SZ + lr * HSTR + lw + 4],  Brow + gk + lw * 2 + 8);
    cp_commit();
}

__device__ __forceinline__ void h_mma_stage(unsigned asu, unsigned bsu,
                                            float acc[4][4][4],
                                            int wm, int wn, int lane) {
    unsigned aAddr = asu + (unsigned)((wm + (lane & 15)) * HSTR) * 4u
                   + (unsigned)(lane >> 4) * 16u;
    unsigned bAddr = bsu + (unsigned)((wn + (lane & 7)) * HSTR) * 4u
                   + (unsigned)((lane >> 3) & 1) * 16u;
    #pragma unroll
    for (int ks = 0; ks < 2; ks++) {
        unsigned koff = (unsigned)ks * 32u;
        unsigned af[4][4], bf[4][2];
        #pragma unroll
        for (int mt = 0; mt < 4; mt++)
            ldsm4(af[mt][0], af[mt][1], af[mt][2], af[mt][3],
                  aAddr + (unsigned)(mt * 16 * HSTR) * 4u + koff);
        #pragma unroll
        for (int nt = 0; nt < 4; nt++)
            ldsm2(bf[nt][0], bf[nt][1],
                  bAddr + (unsigned)(nt * 8 * HSTR) * 4u + koff);
        #pragma unroll
        for (int mt = 0; mt < 4; mt++)
            #pragma unroll
            for (int nt = 0; nt < 4; nt++)
                mma_f16(acc[mt][nt], af[mt][0], af[mt][1], af[mt][2], af[mt][3],
                        bf[nt][0], bf[nt][1]);
    }
}

// ---- dense f16 GEMM: out = A @ Wt^T (+bias)(+resid). Cf fp32 or Ch f16. -----
__global__ void __launch_bounds__(256)
gemm_f16(const __half* __restrict__ A, const __half* __restrict__ Wt,
         float* __restrict__ Cf, __half* __restrict__ Ch, int N, int K,
         const float* __restrict__ bias, const float* __restrict__ resid) {
    extern __shared__ unsigned smg[];
    unsigned* As = smg;
    unsigned* Bs = smg + 3 * HS_SZ;
    unsigned asu = (unsigned)__cvta_generic_to_shared(As);
    unsigned bsu = (unsigned)__cvta_generic_to_shared(Bs);
    int tid = threadIdx.x, warp = tid >> 5, lane = tid & 31;
    int gid = lane >> 2, tg = lane & 3;
    int wm = (warp >> 2) * 64, wn = (warp & 3) * 32;
    int m0 = blockIdx.y * 128, n0 = blockIdx.x * 128;

    float acc[4][4][4];
    #pragma unroll
    for (int i = 0; i < 4; i++)
        #pragma unroll
        for (int j = 0; j < 4; j++)
            #pragma unroll
            for (int q = 0; q < 4; q++) acc[i][j][q] = 0.f;

    int lr = tid >> 1, lw = (tid & 1) * 8;
    const __half* Arow = A + (size_t)(m0 + lr) * K;
    const __half* Brow = Wt + (size_t)(n0 + lr) * K;

    h_load(As, Bs, 0, 0,   Arow, 1, Brow, lr, lw);
    h_load(As, Bs, 1, BKh, Arow, 1, Brow, lr, lw);

    int nk = K / BKh;
    for (int kt = 0; kt < nk; kt++) {
        int s = kt % 3;
        cp_wait1(); __syncthreads();
        if (kt + 2 < nk) {
            h_load(As, Bs, (kt + 2) % 3, (kt + 2) * BKh, Arow, 1, Brow, lr, lw);
        } else {
            cp_commit();
        }
        h_mma_stage(asu + s * HS_SZ * 4, bsu + s * HS_SZ * 4, acc, wm, wn, lane);
    }

    #pragma unroll
    for (int mt = 0; mt < 4; mt++) {
        int mA = m0 + wm + mt * 16 + gid, mB = mA + 8;
        #pragma unroll
        for (int nt = 0; nt < 4; nt++) {
            int n = n0 + wn + nt * 8 + tg * 2;
            float v0 = acc[mt][nt][0], v1 = acc[mt][nt][1];
            float v2 = acc[mt][nt][2], v3 = acc[mt][nt][3];
            if (bias) {
                float b0 = bias[n], b1 = bias[n + 1];
                v0 += b0; v1 += b1; v2 += b0; v3 += b1;
            }
            if (resid) {
                v0 += resid[(size_t)mA * N + n];
                v1 += resid[(size_t)mA * N + n + 1];
                v2 += resid[(size_t)mB * N + n];
                v3 += resid[(size_t)mB * N + n + 1];
            }
            if (Ch) {
                *(__half2*)&Ch[(size_t)mA * N + n] = f2h2(v0, v1);
                *(__half2*)&Ch[(size_t)mB * N + n] = f2h2(v2, v3);
            } else {
                Cf[(size_t)mA * N + n]     = v0;
                Cf[(size_t)mA * N + n + 1] = v1;
                Cf[(size_t)mB * N + n]     = v2;
                Cf[(size_t)mB * N + n + 1] = v3;
            }
        }
    }
}

// ---- MoE GEMM1: Y1(f16) = gelu(gather(Hh) @ w1T^T + b1) ---------------------
__global__ void __launch_bounds__(256)
moe1_f16(const __half* __restrict__ Hh, const __half* __restrict__ W1T,
         const float* __restrict__ B1, __half* __restrict__ Y1) {
    int e = blockIdx.z;
    int cnt = g_cnt[e];
    int m0 = blockIdx.y * 128;
    if (m0 >= cnt) return;
    int off = g_off[e];

    extern __shared__ unsigned smg[];
    unsigned* As = smg;
    unsigned* Bs = smg + 3 * HS_SZ;
    unsigned asu = (unsigned)__cvta_generic_to_shared(As);
    unsigned bsu = (unsigned)__cvta_generic_to_shared(Bs);
    __shared__ int toks[128];
    int tid = threadIdx.x, warp = tid >> 5, lane = tid & 31;
    int gid = lane >> 2, tg = lane & 3;
    int wm = (warp >> 2) * 64, wn = (warp & 3) * 32;
    if (tid < 128) {
        int m = m0 + tid;
        toks[tid] = (m < cnt) ? g_sorted[off + m] : -1;
    }
    __syncthreads();

    float acc[4][4][4];
    #pragma unroll
    for (int i = 0; i < 4; i++)
        #pragma unroll
        for (int j = 0; j < 4; j++)
            #pragma unroll
            for (int q = 0; q < 4; q++) acc[i][j][q] = 0.f;

    int n0 = blockIdx.x * 128;
    int lr = tid >> 1, lw = (tid & 1) * 8;
    int tok = toks[lr];
    const __half* Arow = Hh + (size_t)(tok >= 0 ? tok : 0) * Dm;
    const __half* Brow = W1T + (size_t)e * FFd * Dm + (size_t)(n0 + lr) * Dm;
    int okA = tok >= 0;

    h_load(As, Bs, 0, 0,   Arow, okA, Brow, lr, lw);
    h_load(As, Bs, 1, BKh, Arow, okA, Brow, lr, lw);

    int nk = Dm / BKh;
    for (int kt = 0; kt < nk; kt++) {
        int s = kt % 3;
        cp_wait1(); __syncthreads();
        if (kt + 2 < nk) {
            h_load(As, Bs, (kt + 2) % 3, (kt + 2) * BKh, Arow, okA, Brow, lr, lw);
        } else {
            cp_commit();
        }
        h_mma_stage(asu + s * HS_SZ * 4, bsu + s * HS_SZ * 4, acc, wm, wn, lane);
    }

    #pragma unroll
    for (int mt = 0; mt < 4; mt++) {
        int gmA = m0 + wm + mt * 16 + gid, gmB = gmA + 8;
        #pragma unroll
        for (int nt = 0; nt < 4; nt++) {
            int n = n0 + wn + nt * 8 + tg * 2;
            float b0 = B1[e * FFd + n], b1 = B1[e * FFd + n + 1];
            if (gmA < cnt) {
                float v0 = gelu_exact(acc[mt][nt][0] + b0);
                float v1 = gelu_exact(acc[mt][nt][1] + b1);
                *(__half2*)&Y1[(size_t)(off + gmA) * FFd + n] = f2h2(v0, v1);
            }
            if (gmB < cnt) {
                float v2 = gelu_exact(acc[mt][nt][2] + b0);
                float v3 = gelu_exact(acc[mt][nt][3] + b1);
                *(__half2*)&Y1[(size_t)(off + gmB) * FFd + n] = f2h2(v2, v3);
            }
        }
    }
}

// ---- MoE GEMM2: OUT(fp32)[tok] += gelu(Y1 @ w2T^T + b2) ---------------------
__global__ void __launch_bounds__(256)
moe2_f16(const __half* __restrict__ Y1, const __half* __restrict__ W2T,
         const float* __restrict__ B2, float* __restrict__ OUT) {
    int e = blockIdx.z;
    int cnt = g_cnt[e];
    int m0 = blockIdx.y * 128;
    if (m0 >= cnt) return;
    int off = g_off[e];

    extern __shared__ unsigned smg[];
    unsigned* As = smg;
    unsigned* Bs = smg + 3 * HS_SZ;
    unsigned asu = (unsigned)__cvta_generic_to_shared(As);
    unsigned bsu = (unsigned)__cvta_generic_to_shared(Bs);
    __shared__ int toks[128];
    int tid = threadIdx.x, warp = tid >> 5, lane = tid & 31;
    int gid = lane >> 2, tg = lane & 3;
    int wm = (warp >> 2) * 64, wn = (warp & 3) * 32;
    if (tid < 128) {
        int m = m0 + tid;
        toks[tid] = (m < cnt) ? g_sorted[off + m] : -1;
    }
    __syncthreads();

    float acc[4][4][4];
    #pragma unroll
    for (int i = 0; i < 4; i++)
        #pragma unroll
        for (int j = 0; j < 4; j++)
            #pragma unroll
            for (int q = 0; q < 4; q++) acc[i][j][q] = 0.f;

    int n0 = blockIdx.x * 128;
    int lr = tid >> 1, lw = (tid & 1) * 8;
    int okA = (m0 + lr) < cnt;
    const __half* Arow = Y1 + (size_t)(off + (okA ? m0 + lr : 0)) * FFd;
    const __half* Brow = W2T + (size_t)e * Dm * FFd + (size_t)(n0 + lr) * FFd;

    h_load(As, Bs, 0, 0,   Arow, okA, Brow, lr, lw);
    h_load(As, Bs, 1, BKh, Arow, okA, Brow, lr, lw);

    int nk = FFd / BKh;
    for (int kt = 0; kt < nk; kt++) {
        int s = kt % 3;
        cp_wait1(); __syncthreads();
        if (kt + 2 < nk) {
            h_load(As, Bs, (kt + 2) % 3, (kt + 2) * BKh, Arow, okA, Brow, lr, lw);
        } else {
            cp_commit();
        }
        h_mma_stage(asu + s * HS_SZ * 4, bsu + s * HS_SZ * 4, acc, wm, wn, lane);
    }

    #pragma unroll
    for (int mt = 0; mt < 4; mt++) {
        int lmA = wm + mt * 16 + gid;
        int gmA = m0 + lmA, gmB = gmA + 8;
        int tA = toks[lmA], tB = toks[lmA + 8];
        #pragma unroll
        for (int nt = 0; nt < 4; nt++) {
            int n = n0 + wn + nt * 8 + tg * 2;
            float b0 = B2[e * Dm + n], b1 = B2[e * Dm + n + 1];
            if (gmA < cnt) {
                OUT[(size_t)tA * Dm + n]     += gelu_exact(acc[mt][nt][0] + b0);
                OUT[(size_t)tA * Dm + n + 1] += gelu_exact(acc[mt][nt][1] + b1);
            }
            if (gmB < cnt) {
                OUT[(size_t)tB * Dm + n]     += gelu_exact(acc[mt][nt][2] + b0);
                OUT[(size_t)tB * Dm + n + 1] += gelu_exact(acc[mt][nt][3] + b1);
            }
        }
    }
}

// =============================================================================
// f16 flash attention. Per block = (b,h) x 64 Q rows, 128 thr = 4 warps,
// each warp 16 Q rows. f16 mma m16n8k16, ldmatrix (V via .trans).
// smem tiles: 64 rows x 72 halves (144B rows, 16B aligned).
// =============================================================================
#define QST 72
#define TILE_H (64 * QST)                  // halves per tile
#define FA_SMEM (5 * TILE_H * 2)           // Q + 2K + 2V

__global__ void flash_f16(const __half* __restrict__ QKV, __half* __restrict__ O) {
    extern __shared__ __half fsm[];
    __half* Qs = fsm;                       // reused as P
    __half* Ks = fsm + TILE_H;              // 2 bufs
    __half* Vs = fsm + 3 * TILE_H;          // 2 bufs
    unsigned qsu = (unsigned)__cvta_generic_to_shared(Qs);
    unsigned ksu = (unsigned)__cvta_generic_to_shared(Ks);
    unsigned vsu = (unsigned)__cvta_generic_to_shared(Vs);

    int bh = blockIdx.y;
    int b = bh / Hn, h = bh % Hn;
    int m0 = blockIdx.x * 64;
    int tid = threadIdx.x;
    int warp = tid >> 5, lane = tid & 31;
    int gid = lane >> 2, tg = lane & 3;
    int wm = warp * 16;

    // --- load Q tile (64 rows x 64 halves = 8 x 16B chunks per row) ---
    #pragma unroll
    for (int l = 0; l < 4; l++) {
        int idx = tid + l * 128, r = idx >> 3, c = idx & 7;
        cp16(&Qs[r * QST + c * 8],
             QKV + (size_t)(b * Sq + m0 + r) * 2304 + h * HDm + c * 8);
    }
    cp_commit(); cp_wait0(); __syncthreads();

    // Q fragments: 4 ksteps x 4 regs, ldsm4
    unsigned aq[4][4];
    {
        unsigned qAddr = qsu + (unsigned)((wm + (lane & 15)) * QST) * 2u
                       + (unsigned)(lane >> 4) * 16u;
        #pragma unroll
        for (int ks = 0; ks < 4; ks++)
            ldsm4(aq[ks][0], aq[ks][1], aq[ks][2], aq[ks][3], qAddr + (unsigned)ks * 32u);
    }
    __syncthreads();  // Qs free -> P staging

    float mr0 = -1e30f, mr1 = -1e30f, lr0 = 0.f, lr1 = 0.f;
    float o[8][4];
    #pragma unroll
    for (int nt = 0; nt < 8; nt++)
        #pragma unroll
        for (int q = 0; q < 4; q++) o[nt][q] = 0.f;

    // prologue: chunk 0 -> buf 0
    #pragma unroll
    for (int l = 0; l < 4; l++) {
        int idx = tid + l * 128, r = idx >> 3, c = idx & 7;
        cp16(&Ks[r * QST + c * 8],
             QKV + (size_t)(b * Sq + r) * 2304 + Dm + h * HDm + c * 8);
        cp16(&Vs[r * QST + c * 8],
             QKV + (size_t)(b * Sq + r) * 2304 + 2 * Dm + h * HDm + c * 8);
    }
    cp_commit();

    for (int c = 0; c < 8; c++) {
        int buf = c & 1;
        if (c + 1 < 8) {
            int nb = buf ^ 1;
            #pragma unroll
            for (int l = 0; l < 4; l++) {
                int idx = tid + l * 128, r = idx >> 3, cc = idx & 7;
                cp16(&Ks[nb * TILE_H + r * QST + cc * 8],
                     QKV + (size_t)(b * Sq + (c + 1) * 64 + r) * 2304 + Dm + h * HDm + cc * 8);
                cp16(&Vs[nb * TILE_H + r * QST + cc * 8],
                     QKV + (size_t)(b * Sq + (c + 1) * 64 + r) * 2304 + 2 * Dm + h * HDm + cc * 8);
            }
            cp_commit();
            cp_wait1();
        } else {
            cp_wait0();
        }
        __syncthreads();
        unsigned kbu = ksu + (unsigned)(buf * TILE_H) * 2u;
        unsigned vbu = vsu + (unsigned)(buf * TILE_H) * 2u;

        // --- S = Q @ K^T : 4 ksteps x 8 ntiles ---
        float s[8][4];
        #pragma unroll
        for (int nt = 0; nt < 8; nt++)
            #pragma unroll
            for (int q = 0; q < 4; q++) s[nt][q] = 0.f;
        {
            unsigned kAddr = kbu + (unsigned)((lane & 7) * QST) * 2u
                           + (unsigned)((lane >> 3) & 1) * 16u;
            #pragma unroll
            for (int ks = 0; ks < 4; ks++) {
                unsigned koff = (unsigned)ks * 32u;
                #pragma unroll
                for (int nt = 0; nt < 8; nt++) {
                    unsigned b0, b1;
                    ldsm2(b0, b1, kAddr + (unsigned)(nt * 8 * QST) * 2u + koff);
                    mma_f16(s[nt], aq[ks][0], aq[ks][1], aq[ks][2], aq[ks][3], b0, b1);
                }
            }
        }

        // --- online softmax ---
        const float sc = 0.125f;
        float mx0 = -1e30f, mx1 = -1e30f;
        #pragma unroll
        for (int nt = 0; nt < 8; nt++) {
            s[nt][0] *= sc; s[nt][1] *= sc; s[nt][2] *= sc; s[nt][3] *= sc;
            mx0 = fmaxf(mx0, fmaxf(s[nt][0], s[nt][1]));
            mx1 = fmaxf(mx1, fmaxf(s[nt][2], s[nt][3]));
        }
        mx0 = fmaxf(mx0, __shfl_xor_sync(0xffffffffu, mx0, 1));
        mx0 = fmaxf(mx0, __shfl_xor_sync(0xffffffffu, mx0, 2));
        mx1 = fmaxf(mx1, __shfl_xor_sync(0xffffffffu, mx1, 1));
        mx1 = fmaxf(mx1, __shfl_xor_sync(0xffffffffu, mx1, 2));
        float mn0 = fmaxf(mr0, mx0), mn1 = fmaxf(mr1, mx1);
        float a0 = __expf(mr0 - mn0), a1 = __expf(mr1 - mn1);
        float sum0 = 0.f, sum1 = 0.f;
        #pragma unroll
        for (int nt = 0; nt < 8; nt++) {
            s[nt][0] = __expf(s[nt][0] - mn0);
            s[nt][1] = __expf(s[nt][1] - mn0);
            s[nt][2] = __expf(s[nt][2] - mn1);
            s[nt][3] = __expf(s[nt][3] - mn1);
            sum0 += s[nt][0] + s[nt][1];
            sum1 += s[nt][2] + s[nt][3];
        }
        sum0 += __shfl_xor_sync(0xffffffffu, sum0, 1);
        sum0 += __shfl_xor_sync(0xffffffffu, sum0, 2);
        sum1 += __shfl_xor_sync(0xffffffffu, sum1, 1);
        sum1 += __shfl_xor_sync(0xffffffffu, sum1, 2);
        lr0 = lr0 * a0 + sum0;
        lr1 = lr1 * a1 + sum1;
        mr0 = mn0; mr1 = mn1;
        #pragma unroll
        for (int nt = 0; nt < 8; nt++) {
            o[nt][0] *= a0; o[nt][1] *= a0;
            o[nt][2] *= a1; o[nt][3] *= a1;
        }

        // --- stage P (f16) into Qs rows [wm..wm+16) ---
        __half* Ps = Qs;
        #pragma unroll
        for (int nt = 0; nt < 8; nt++) {
            int cc = nt * 8 + tg * 2;
            *(__half2*)&Ps[(wm + gid) * QST + cc]     = f2h2(s[nt][0], s[nt][1]);
            *(__half2*)&Ps[(wm + gid + 8) * QST + cc] = f2h2(s[nt][2], s[nt][3]);
        }
        __syncwarp();

        // --- O += P @ V : A=P via ldsm4, B=V^T via ldsm2.trans ---
        {
            unsigned pAddr = qsu + (unsigned)((wm + (lane & 15)) * QST) * 2u
                           + (unsigned)(lane >> 4) * 16u;
            // trans lane map: lanes 0-7 -> stored V rows k+0..7, 8-15 -> k+8..15
            unsigned vRow = (unsigned)((lane & 7) + ((lane >> 3) & 1) * 8);
            #pragma unroll
            for (int ks = 0; ks < 4; ks++) {
                unsigned pf0, pf1, pf2, pf3;
                ldsm4(pf0, pf1, pf2, pf3, pAddr + (unsigned)ks * 32u);
                unsigned vBase = vbu + (unsigned)((ks * 16 + vRow) * QST) * 2u;
                #pragma unroll
                for (int nt = 0; nt < 8; nt++) {
                    unsigned v0, v1;
                    ldsm2t(v0, v1, vBase + (unsigned)(nt * 8) * 2u);
                    mma_f16(o[nt], pf0, pf1, pf2, pf3, v0, v1);
                }
            }
        }
        __syncthreads();
    }

    float inv0 = 1.0f / lr0, inv1 = 1.0f / lr1;
    int rA = b * Sq + m0 + wm + gid, rB = rA + 8;
    #pragma unroll
    for (int nt = 0; nt < 8; nt++) {
        int cc = h * HDm + nt * 8 + tg * 2;
        *(__half2*)&O[(size_t)rA * Dm + cc] = f2h2(o[nt][0] * inv0, o[nt][1] * inv0);
        *(__half2*)&O[(size_t)rB * Dm + cc] = f2h2(o[nt][2] * inv1, o[nt][3] * inv1);
    }
}

// ---------------- router (exact fp32 logits) ----------------------------------
__global__ void route_kernel(const float* __restrict__ H2,
                             const float* __restrict__ SW,
                             const float* __restrict__ SB) {
    int warp = (blockIdx.x * blockDim.x + threadIdx.x) >> 5;
    int lane = threadIdx.x & 31;
    if (warp >= TOK) return;
    const float* hrow = H2 + (size_t)warp * Dm;
    float acc[En];
    #pragma unroll
    for (int e = 0; e < En; e++) acc[e] = 0.f;
    for (int d = lane; d < Dm; d += 32) {
        float hv = hrow[d];
        const float* w = SW + d * En;
        #pragma unroll
        for (int e = 0; e < En; e++) acc[e] += hv * w[e];
    }
    #pragma unroll
    for (int e = 0; e < En; e++)
        #pragma unroll
        for (int o = 16; o; o >>= 1)
            acc[e] += __shfl_xor_sync(0xffffffffu, acc[e], o);
    if (lane == 0) {
        float best = acc[0] + SB[0];
        int be = 0;
        #pragma unroll
        for (int e = 1; e < En; e++) {
            float v = acc[e] + SB[e];
            if (v > best) { best = v; be = e; }
        }
        g_routes[warp] = be;
        atomicAdd(&g_cnt[be], 1);
    }
}

__global__ void offsets_kernel() {
    if (threadIdx.x == 0) {
        int acc = 0;
        for (int e = 0; e < En; e++) { g_off[e] = acc; acc += g_cnt[e]; }
    }
}

__global__ void scatter_kernel() {
    int t = blockIdx.x * blockDim.x + threadIdx.x;
    if (t >= TOK) return;
    int e = g_routes[t];
    int pos = atomicAdd(&g_cur[e], 1);
    g_sorted[g_off[e] + pos] = t;
}

// ---------------- launch ------------------------------------------------------
extern "C" void kernel_launch(void* const* d_in, const int* in_sizes, int n_in,
                              void* d_out, int out_size) {
    const float* x       = (const float*)d_in[0];
    // d_in[1] = indexes_list (unused by reference math)
    const float* ln1_g   = (const float*)d_in[2];
    const float* ln1_b   = (const float*)d_in[3];
    const float* qkv_w   = (const float*)d_in[4];
    const float* proj_w  = (const float*)d_in[5];
    const float* proj_b  = (const float*)d_in[6];
    const float* ln2_g   = (const float*)d_in[7];
    const float* ln2_b   = (const float*)d_in[8];
    const float* sw_w    = (const float*)d_in[9];
    const float* sw_b    = (const float*)d_in[10];
    const float* w1      = (const float*)d_in[11];
    const float* b1      = (const float*)d_in[12];
    const float* w2      = (const float*)d_in[13];
    const float* b2      = (const float*)d_in[14];
    float* out = (float*)d_out;

    __half *gh, *gqkv, *go, *ghh, *gy1, *gqT, *gpT, *g1T, *g2T;
    float *gh2;
    cudaGetSymbolAddress((void**)&gh,   g_h);
    cudaGetSymbolAddress((void**)&gqkv, g_qkv);
    cudaGetSymbolAddress((void**)&go,   g_o);
    cudaGetSymbolAddress((void**)&gh2,  g_h2);
    cudaGetSymbolAddress((void**)&ghh,  g_hh);
    cudaGetSymbolAddress((void**)&gy1,  g_y1);
    cudaGetSymbolAddress((void**)&gqT,  g_qkvT);
    cudaGetSymbolAddress((void**)&gpT,  g_projT);
    cudaGetSymbolAddress((void**)&g1T,  g_w1T);
    cudaGetSymbolAddress((void**)&g2T,  g_w2T);

    static int smem_set = 0;
    if (!smem_set) {
        cudaFuncSetAttribute(flash_f16, cudaFuncAttributeMaxDynamicSharedMemorySize, FA_SMEM);
        cudaFuncSetAttribute(gemm_f16,  cudaFuncAttributeMaxDynamicSharedMemorySize, GEMM_SMEM_H);
        cudaFuncSetAttribute(moe1_f16,  cudaFuncAttributeMaxDynamicSharedMemorySize, GEMM_SMEM_H);
        cudaFuncSetAttribute(moe2_f16,  cudaFuncAttributeMaxDynamicSharedMemorySize, GEMM_SMEM_H);
        smem_set = 1;
    }

    reset_kernel<<<1, 32>>>();

    // weight transposes -> f16 [n][k]
    transpose_h<<<dim3(3 * Dm / 32, Dm / 32), dim3(32, 8)>>>(qkv_w, gqT, Dm, 3 * Dm);
    transpose_h<<<dim3(Dm / 32, Dm / 32), dim3(32, 8)>>>(proj_w, gpT, Dm, Dm);
    transpose_h<<<dim3(FFd / 32, Dm / 32, En), dim3(32, 8)>>>(w1, g1T, Dm, FFd);
    transpose_h<<<dim3(Dm / 32, FFd / 32, En), dim3(32, 8)>>>(w2, g2T, FFd, Dm);

    // ln1 -> f16
    ln_kernel<<<TOK, 256>>>(x, ln1_g, ln1_b, nullptr, gh);
    // qkv = h @ qkv_w (f16 mma) -> f16 output
    gemm_f16<<<dim3(3 * Dm / 128, TOK / 128), 256, GEMM_SMEM_H>>>(
        gh, gqT, nullptr, gqkv, 3 * Dm, Dm, nullptr, nullptr);
    // fused attention (f16) -> f16 output
    flash_f16<<<dim3(Sq / 64, BHN), 128, FA_SMEM>>>(gqkv, go);
    // xmid = x + o @ proj_w + proj_b -> d_out (exact fp32)
    gemm_f16<<<dim3(Dm / 128, TOK / 128), 256, GEMM_SMEM_H>>>(
        go, gpT, out, nullptr, Dm, Dm, proj_b, x);
    // ln2 -> fp32 (router) + f16 (moe1 A)
    ln_kernel<<<TOK, 256>>>(out, ln2_g, ln2_b, gh2, ghh);
    // routing
    route_kernel<<<512, 256>>>(gh2, sw_w, sw_b);
    offsets_kernel<<<1, 32>>>();
    scatter_kernel<<<TOK / 256, 256>>>();
    // MoE expert GEMMs (f16 mma)
    moe1_f16<<<dim3(FFd / 128, TOK / 128, En), 256, GEMM_SMEM_H>>>(ghh, g1T, b1, gy1);
    moe2_f16<<<dim3(Dm / 128, TOK / 128, En), 256, GEMM_SMEM_H>>>(gy1, g2T, b2, out);
}

// round 17
// speedup vs baseline: 1.4035x; 1.0118x over previous
#include <cuda_runtime.h>
#include <cuda_fp16.h>
#include <stdint.h>
#include <math.h>

#define Bsz 8
#define Sq  512
#define Dm  768
#define Hn  12
#define HDm 64
#define En  8
#define FFd 3072
#define TOK 4096
#define BHN 96
#define BKh 32

// ---------------- scratch (device globals; no allocations allowed) ----------
__device__ __half g_h[TOK * Dm];             // ln1 out (f16)
__device__ __half g_qkv[TOK * 3 * Dm];       // qkv (f16)
__device__ __half g_o[TOK * Dm];             // flash out (f16)
__device__ float  g_h2[TOK * Dm];            // ln2 out exact (router)
__device__ __half g_hh[TOK * Dm];            // ln2 out f16 (moe1 A)
__device__ __half g_y1[(size_t)TOK * FFd];   // moe hidden (f16)
__device__ __half g_qkvT[3 * Dm * Dm];
__device__ __half g_projT[Dm * Dm];
__device__ __half g_w1T[(size_t)En * FFd * Dm];
__device__ __half g_w2T[(size_t)En * Dm * FFd];
__device__ int    g_routes[TOK];
__device__ int    g_cnt[En];
__device__ int    g_off[En];
__device__ int    g_cur[En];
__device__ int    g_sorted[TOK];

// ---------------- helpers ---------------------------------------------------
__device__ __forceinline__ float gelu_exact(float x) {
    return 0.5f * x * (1.0f + erff(x * 0.70710678118654752f));
}
__device__ __forceinline__ void mma_f16(float c[4],
                                        unsigned a0, unsigned a1, unsigned a2, unsigned a3,
                                        unsigned b0, unsigned b1) {
    asm volatile(
        "mma.sync.aligned.m16n8k16.row.col.f32.f16.f16.f32 "
        "{%0,%1,%2,%3},{%4,%5,%6,%7},{%8,%9},{%0,%1,%2,%3};"
        : "+f"(c[0]), "+f"(c[1]), "+f"(c[2]), "+f"(c[3])
        : "r"(a0), "r"(a1), "r"(a2), "r"(a3), "r"(b0), "r"(b1));
}
__device__ __forceinline__ void ldsm4(unsigned& r0, unsigned& r1, unsigned& r2, unsigned& r3,
                                      unsigned addr) {
    asm volatile("ldmatrix.sync.aligned.m8n8.x4.shared.b16 {%0,%1,%2,%3}, [%4];"
        : "=r"(r0), "=r"(r1), "=r"(r2), "=r"(r3) : "r"(addr));
}
__device__ __forceinline__ void ldsm2(unsigned& r0, unsigned& r1, unsigned addr) {
    asm volatile("ldmatrix.sync.aligned.m8n8.x2.shared.b16 {%0,%1}, [%2];"
        : "=r"(r0), "=r"(r1) : "r"(addr));
}
__device__ __forceinline__ void ldsm2t(unsigned& r0, unsigned& r1, unsigned addr) {
    asm volatile("ldmatrix.sync.aligned.m8n8.x2.trans.shared.b16 {%0,%1}, [%2];"
        : "=r"(r0), "=r"(r1) : "r"(addr));
}

__device__ __forceinline__ void cp16(void* d, const void* s) {
    unsigned sd = (unsigned)__cvta_generic_to_shared(d);
    asm volatile("cp.async.cg.shared.global [%0], [%1], 16;" :: "r"(sd), "l"(s));
}
__device__ __forceinline__ void cp16z(void* d, const void* s, int pred) {
    unsigned sd = (unsigned)__cvta_generic_to_shared(d);
    int sz = pred ? 16 : 0;
    asm volatile("cp.async.cg.shared.global [%0], [%1], 16, %2;" :: "r"(sd), "l"(s), "r"(sz));
}
__device__ __forceinline__ void cp_commit() { asm volatile("cp.async.commit_group;"); }
__device__ __forceinline__ void cp_wait0()  { asm volatile("cp.async.wait_group 0;"); }
__device__ __forceinline__ void cp_wait1()  { asm volatile("cp.async.wait_group 1;"); }

__device__ __forceinline__ __half2 f2h2(float a, float b) {
    return __halves2half2(__float2half_rn(a), __float2half_rn(b));
}

// ---------------- reset counters --------------------------------------------
__global__ void reset_kernel() {
    int t = threadIdx.x;
    if (t < En) { g_cnt[t] = 0; g_cur[t] = 0; }
}

// ---------------- transpose + f16 convert: Wt[n][k] = h(W[k][n]) ------------
__global__ void transpose_h(const float* __restrict__ W, __half* __restrict__ Wt,
                            int K, int N) {
    size_t eo = (size_t)blockIdx.z * K * N;
    W += eo; Wt += eo;
    __shared__ float t[32][33];
    int n0 = blockIdx.x * 32, k0 = blockIdx.y * 32;
    int tx = threadIdx.x, ty = threadIdx.y;
    #pragma unroll
    for (int l = 0; l < 4; l++)
        t[ty + l * 8][tx] = W[(size_t)(k0 + ty + l * 8) * N + n0 + tx];
    __syncthreads();
    #pragma unroll
    for (int l = 0; l < 4; l++)
        Wt[(size_t)(n0 + ty + l * 8) * K + k0 + tx] = __float2half_rn(t[tx][ty + l * 8]);
}

// ---------------- layernorm: outputs fp32 (opt) and/or f16 (opt) ------------
__global__ void ln_kernel(const float* __restrict__ X,
                          const float* __restrict__ gam,
                          const float* __restrict__ bet,
                          float* __restrict__ Yf, __half* __restrict__ Yh) {
    int row = blockIdx.x;
    int tid = threadIdx.x;
    const float* x = X + (size_t)row * Dm;
    float v0 = x[tid], v1 = x[tid + 256], v2 = x[tid + 512];

    __shared__ float red[256];
    red[tid] = v0 + v1 + v2; __syncthreads();
    #pragma unroll
    for (int st = 128; st > 0; st >>= 1) {
        if (tid < st) red[tid] += red[tid + st];
        __syncthreads();
    }
    float mu = red[0] / (float)Dm;
    __syncthreads();

    float d0 = v0 - mu, d1 = v1 - mu, d2 = v2 - mu;
    red[tid] = d0 * d0 + d1 * d1 + d2 * d2; __syncthreads();
    #pragma unroll
    for (int st = 128; st > 0; st >>= 1) {
        if (tid < st) red[tid] += red[tid + st];
        __syncthreads();
    }
    float rstd = rsqrtf(red[0] / (float)Dm + 1e-5f);

    float o0 = d0 * rstd * gam[tid]       + bet[tid];
    float o1 = d1 * rstd * gam[tid + 256] + bet[tid + 256];
    float o2 = d2 * rstd * gam[tid + 512] + bet[tid + 512];
    if (Yf) {
        float* y = Yf + (size_t)row * Dm;
        y[tid] = o0; y[tid + 256] = o1; y[tid + 512] = o2;
    }
    if (Yh) {
        __half* y = Yh + (size_t)row * Dm;
        y[tid]       = __float2half_rn(o0);
        y[tid + 256] = __float2half_rn(o1);
        y[tid + 512] = __float2half_rn(o2);
    }
}

// =============================================================================
// f16 GEMM (ldmatrix): BM=128, BN=128, BK=32, 3-stage ring.
// =============================================================================
#define HSTR 20
#define HS_SZ (128 * HSTR)
#define GEMM_SMEM_H (2 * 3 * HS_SZ * 4)

__device__ __forceinline__ void h_load(unsigned* As, unsigned* Bs, int st, int gk,
                                       const __half* Arow, int okA,
                                       const __half* Brow, int lr, int lw) {
    cp16z(&As[st * HS_SZ + lr * HSTR + lw],     Arow + gk + lw * 2,     okA);
    cp16z(&As[st * HS_SZ + lr * HSTR + lw + 4], Arow + gk + lw * 2 + 8, okA);
    cp16(&Bs[st * HS_SZ + lr * HSTR + lw],      Brow + gk + lw * 2);
    cp16(&Bs[st * HS_SZ + lr * HSTR + lw + 4],  Brow + gk + lw * 2 + 8);
    cp_commit();
}

__device__ __forceinline__ void h_mma_stage(unsigned asu, unsigned bsu,
                                            float acc[4][4][4],
                                            int wm, int wn, int lane) {
    unsigned aAddr = asu + (unsigned)((wm + (lane & 15)) * HSTR) * 4u
                   + (unsigned)(lane >> 4) * 16u;
    unsigned bAddr = bsu + (unsigned)((wn + (lane & 7)) * HSTR) * 4u
                   + (unsigned)((lane >> 3) & 1) * 16u;
    #pragma unroll
    for (int ks = 0; ks < 2; ks++) {
        unsigned koff = (unsigned)ks * 32u;
        unsigned af[4][4], bf[4][2];
        #pragma unroll
        for (int mt = 0; mt < 4; mt++)
            ldsm4(af[mt][0], af[mt][1], af[mt][2], af[mt][3],
                  aAddr + (unsigned)(mt * 16 * HSTR) * 4u + koff);
        #pragma unroll
        for (int nt = 0; nt < 4; nt++)
            ldsm2(bf[nt][0], bf[nt][1],
                  bAddr + (unsigned)(nt * 8 * HSTR) * 4u + koff);
        #pragma unroll
        for (int mt = 0; mt < 4; mt++)
            #pragma unroll
            for (int nt = 0; nt < 4; nt++)
                mma_f16(acc[mt][nt], af[mt][0], af[mt][1], af[mt][2], af[mt][3],
                        bf[nt][0], bf[nt][1]);
    }
}

// ---- dense f16 GEMM: out = A @ Wt^T (+bias)(+resid). Cf fp32 or Ch f16. -----
__global__ void __launch_bounds__(256)
gemm_f16(const __half* __restrict__ A, const __half* __restrict__ Wt,
         float* __restrict__ Cf, __half* __restrict__ Ch, int N, int K,
         const float* __restrict__ bias, const float* __restrict__ resid) {
    extern __shared__ unsigned smg[];
    unsigned* As = smg;
    unsigned* Bs = smg + 3 * HS_SZ;
    unsigned asu = (unsigned)__cvta_generic_to_shared(As);
    unsigned bsu = (unsigned)__cvta_generic_to_shared(Bs);
    int tid = threadIdx.x, warp = tid >> 5, lane = tid & 31;
    int gid = lane >> 2, tg = lane & 3;
    int wm = (warp >> 2) * 64, wn = (warp & 3) * 32;
    int m0 = blockIdx.y * 128, n0 = blockIdx.x * 128;

    float acc[4][4][4];
    #pragma unroll
    for (int i = 0; i < 4; i++)
        #pragma unroll
        for (int j = 0; j < 4; j++)
            #pragma unroll
            for (int q = 0; q < 4; q++) acc[i][j][q] = 0.f;

    int lr = tid >> 1, lw = (tid & 1) * 8;
    const __half* Arow = A + (size_t)(m0 + lr) * K;
    const __half* Brow = Wt + (size_t)(n0 + lr) * K;

    h_load(As, Bs, 0, 0,   Arow, 1, Brow, lr, lw);
    h_load(As, Bs, 1, BKh, Arow, 1, Brow, lr, lw);

    int nk = K / BKh;
    for (int kt = 0; kt < nk; kt++) {
        int s = kt % 3;
        cp_wait1(); __syncthreads();
        if (kt + 2 < nk) {
            h_load(As, Bs, (kt + 2) % 3, (kt + 2) * BKh, Arow, 1, Brow, lr, lw);
        } else {
            cp_commit();
        }
        h_mma_stage(asu + s * HS_SZ * 4, bsu + s * HS_SZ * 4, acc, wm, wn, lane);
    }

    #pragma unroll
    for (int mt = 0; mt < 4; mt++) {
        int mA = m0 + wm + mt * 16 + gid, mB = mA + 8;
        #pragma unroll
        for (int nt = 0; nt < 4; nt++) {
            int n = n0 + wn + nt * 8 + tg * 2;
            float v0 = acc[mt][nt][0], v1 = acc[mt][nt][1];
            float v2 = acc[mt][nt][2], v3 = acc[mt][nt][3];
            if (bias) {
                float b0 = bias[n], b1 = bias[n + 1];
                v0 += b0; v1 += b1; v2 += b0; v3 += b1;
            }
            if (resid) {
                v0 += resid[(size_t)mA * N + n];
                v1 += resid[(size_t)mA * N + n + 1];
                v2 += resid[(size_t)mB * N + n];
                v3 += resid[(size_t)mB * N + n + 1];
            }
            if (Ch) {
                *(__half2*)&Ch[(size_t)mA * N + n] = f2h2(v0, v1);
                *(__half2*)&Ch[(size_t)mB * N + n] = f2h2(v2, v3);
            } else {
                Cf[(size_t)mA * N + n]     = v0;
                Cf[(size_t)mA * N + n + 1] = v1;
                Cf[(size_t)mB * N + n]     = v2;
                Cf[(size_t)mB * N + n + 1] = v3;
            }
        }
    }
}

// ---- MoE GEMM1: Y1(f16) = gelu(gather(Hh) @ w1T^T + b1) ---------------------
__global__ void __launch_bounds__(256)
moe1_f16(const __half* __restrict__ Hh, const __half* __restrict__ W1T,
         const float* __restrict__ B1, __half* __restrict__ Y1) {
    int e = blockIdx.z;
    int cnt = g_cnt[e];
    int m0 = blockIdx.y * 128;
    if (m0 >= cnt) return;
    int off = g_off[e];

    extern __shared__ unsigned smg[];
    unsigned* As = smg;
    unsigned* Bs = smg + 3 * HS_SZ;
    unsigned asu = (unsigned)__cvta_generic_to_shared(As);
    unsigned bsu = (unsigned)__cvta_generic_to_shared(Bs);
    __shared__ int toks[128];
    int tid = threadIdx.x, warp = tid >> 5, lane = tid & 31;
    int gid = lane >> 2, tg = lane & 3;
    int wm = (warp >> 2) * 64, wn = (warp & 3) * 32;
    if (tid < 128) {
        int m = m0 + tid;
        toks[tid] = (m < cnt) ? g_sorted[off + m] : -1;
    }
    __syncthreads();

    float acc[4][4][4];
    #pragma unroll
    for (int i = 0; i < 4; i++)
        #pragma unroll
        for (int j = 0; j < 4; j++)
            #pragma unroll
            for (int q = 0; q < 4; q++) acc[i][j][q] = 0.f;

    int n0 = blockIdx.x * 128;
    int lr = tid >> 1, lw = (tid & 1) * 8;
    int tok = toks[lr];
    const __half* Arow = Hh + (size_t)(tok >= 0 ? tok : 0) * Dm;
    const __half* Brow = W1T + (size_t)e * FFd * Dm + (size_t)(n0 + lr) * Dm;
    int okA = tok >= 0;

    h_load(As, Bs, 0, 0,   Arow, okA, Brow, lr, lw);
    h_load(As, Bs, 1, BKh, Arow, okA, Brow, lr, lw);

    int nk = Dm / BKh;
    for (int kt = 0; kt < nk; kt++) {
        int s = kt % 3;
        cp_wait1(); __syncthreads();
        if (kt + 2 < nk) {
            h_load(As, Bs, (kt + 2) % 3, (kt + 2) * BKh, Arow, okA, Brow, lr, lw);
        } else {
            cp_commit();
        }
        h_mma_stage(asu + s * HS_SZ * 4, bsu + s * HS_SZ * 4, acc, wm, wn, lane);
    }

    #pragma unroll
    for (int mt = 0; mt < 4; mt++) {
        int gmA = m0 + wm + mt * 16 + gid, gmB = gmA + 8;
        #pragma unroll
        for (int nt = 0; nt < 4; nt++) {
            int n = n0 + wn + nt * 8 + tg * 2;
            float b0 = B1[e * FFd + n], b1 = B1[e * FFd + n + 1];
            if (gmA < cnt) {
                float v0 = gelu_exact(acc[mt][nt][0] + b0);
                float v1 = gelu_exact(acc[mt][nt][1] + b1);
                *(__half2*)&Y1[(size_t)(off + gmA) * FFd + n] = f2h2(v0, v1);
            }
            if (gmB < cnt) {
                float v2 = gelu_exact(acc[mt][nt][2] + b0);
                float v3 = gelu_exact(acc[mt][nt][3] + b1);
                *(__half2*)&Y1[(size_t)(off + gmB) * FFd + n] = f2h2(v2, v3);
            }
        }
    }
}

// ---- MoE GEMM2: OUT(fp32)[tok] += gelu(Y1 @ w2T^T + b2) ---------------------
__global__ void __launch_bounds__(256)
moe2_f16(const __half* __restrict__ Y1, const __half* __restrict__ W2T,
         const float* __restrict__ B2, float* __restrict__ OUT) {
    int e = blockIdx.z;
    int cnt = g_cnt[e];
    int m0 = blockIdx.y * 128;
    if (m0 >= cnt) return;
    int off = g_off[e];

    extern __shared__ unsigned smg[];
    unsigned* As = smg;
    unsigned* Bs = smg + 3 * HS_SZ;
    unsigned asu = (unsigned)__cvta_generic_to_shared(As);
    unsigned bsu = (unsigned)__cvta_generic_to_shared(Bs);
    __shared__ int toks[128];
    int tid = threadIdx.x, warp = tid >> 5, lane = tid & 31;
    int gid = lane >> 2, tg = lane & 3;
    int wm = (warp >> 2) * 64, wn = (warp & 3) * 32;
    if (tid < 128) {
        int m = m0 + tid;
        toks[tid] = (m < cnt) ? g_sorted[off + m] : -1;
    }
    __syncthreads();

    float acc[4][4][4];
    #pragma unroll
    for (int i = 0; i < 4; i++)
        #pragma unroll
        for (int j = 0; j < 4; j++)
            #pragma unroll
            for (int q = 0; q < 4; q++) acc[i][j][q] = 0.f;

    int n0 = blockIdx.x * 128;
    int lr = tid >> 1, lw = (tid & 1) * 8;
    int okA = (m0 + lr) < cnt;
    const __half* Arow = Y1 + (size_t)(off + (okA ? m0 + lr : 0)) * FFd;
    const __half* Brow = W2T + (size_t)e * Dm * FFd + (size_t)(n0 + lr) * FFd;

    h_load(As, Bs, 0, 0,   Arow, okA, Brow, lr, lw);
    h_load(As, Bs, 1, BKh, Arow, okA, Brow, lr, lw);

    int nk = FFd / BKh;
    for (int kt = 0; kt < nk; kt++) {
        int s = kt % 3;
        cp_wait1(); __syncthreads();
        if (kt + 2 < nk) {
            h_load(As, Bs, (kt + 2) % 3, (kt + 2) * BKh, Arow, okA, Brow, lr, lw);
        } else {
            cp_commit();
        }
        h_mma_stage(asu + s * HS_SZ * 4, bsu + s * HS_SZ * 4, acc, wm, wn, lane);
    }

    #pragma unroll
    for (int mt = 0; mt < 4; mt++) {
        int lmA = wm + mt * 16 + gid;
        int gmA = m0 + lmA, gmB = gmA + 8;
        int tA = toks[lmA], tB = toks[lmA + 8];
        #pragma unroll
        for (int nt = 0; nt < 4; nt++) {
            int n = n0 + wn + nt * 8 + tg * 2;
            float b0 = B2[e * Dm + n], b1 = B2[e * Dm + n + 1];
            if (gmA < cnt) {
                OUT[(size_t)tA * Dm + n]     += gelu_exact(acc[mt][nt][0] + b0);
                OUT[(size_t)tA * Dm + n + 1] += gelu_exact(acc[mt][nt][1] + b1);
            }
            if (gmB < cnt) {
                OUT[(size_t)tB * Dm + n]     += gelu_exact(acc[mt][nt][2] + b0);
                OUT[(size_t)tB * Dm + n + 1] += gelu_exact(acc[mt][nt][3] + b1);
            }
        }
    }
}

// =============================================================================
// f16 flash attention (R16, unchanged).
// =============================================================================
#define QST 72
#define TILE_H (64 * QST)
#define FA_SMEM (5 * TILE_H * 2)

__global__ void flash_f16(const __half* __restrict__ QKV, __half* __restrict__ O) {
    extern __shared__ __half fsm[];
    __half* Qs = fsm;
    __half* Ks = fsm + TILE_H;
    __half* Vs = fsm + 3 * TILE_H;
    unsigned qsu = (unsigned)__cvta_generic_to_shared(Qs);
    unsigned ksu = (unsigned)__cvta_generic_to_shared(Ks);
    unsigned vsu = (unsigned)__cvta_generic_to_shared(Vs);

    int bh = blockIdx.y;
    int b = bh / Hn, h = bh % Hn;
    int m0 = blockIdx.x * 64;
    int tid = threadIdx.x;
    int warp = tid >> 5, lane = tid & 31;
    int gid = lane >> 2, tg = lane & 3;
    int wm = warp * 16;

    #pragma unroll
    for (int l = 0; l < 4; l++) {
        int idx = tid + l * 128, r = idx >> 3, c = idx & 7;
        cp16(&Qs[r * QST + c * 8],
             QKV + (size_t)(b * Sq + m0 + r) * 2304 + h * HDm + c * 8);
    }
    cp_commit(); cp_wait0(); __syncthreads();

    unsigned aq[4][4];
    {
        unsigned qAddr = qsu + (unsigned)((wm + (lane & 15)) * QST) * 2u
                       + (unsigned)(lane >> 4) * 16u;
        #pragma unroll
        for (int ks = 0; ks < 4; ks++)
            ldsm4(aq[ks][0], aq[ks][1], aq[ks][2], aq[ks][3], qAddr + (unsigned)ks * 32u);
    }
    __syncthreads();

    float mr0 = -1e30f, mr1 = -1e30f, lr0 = 0.f, lr1 = 0.f;
    float o[8][4];
    #pragma unroll
    for (int nt = 0; nt < 8; nt++)
        #pragma unroll
        for (int q = 0; q < 4; q++) o[nt][q] = 0.f;

    #pragma unroll
    for (int l = 0; l < 4; l++) {
        int idx = tid + l * 128, r = idx >> 3, c = idx & 7;
        cp16(&Ks[r * QST + c * 8],
             QKV + (size_t)(b * Sq + r) * 2304 + Dm + h * HDm + c * 8);
        cp16(&Vs[r * QST + c * 8],
             QKV + (size_t)(b * Sq + r) * 2304 + 2 * Dm + h * HDm + c * 8);
    }
    cp_commit();

    for (int c = 0; c < 8; c++) {
        int buf = c & 1;
        if (c + 1 < 8) {
            int nb = buf ^ 1;
            #pragma unroll
            for (int l = 0; l < 4; l++) {
                int idx = tid + l * 128, r = idx >> 3, cc = idx & 7;
                cp16(&Ks[nb * TILE_H + r * QST + cc * 8],
                     QKV + (size_t)(b * Sq + (c + 1) * 64 + r) * 2304 + Dm + h * HDm + cc * 8);
                cp16(&Vs[nb * TILE_H + r * QST + cc * 8],
                     QKV + (size_t)(b * Sq + (c + 1) * 64 + r) * 2304 + 2 * Dm + h * HDm + cc * 8);
            }
            cp_commit();
            cp_wait1();
        } else {
            cp_wait0();
        }
        __syncthreads();
        unsigned kbu = ksu + (unsigned)(buf * TILE_H) * 2u;
        unsigned vbu = vsu + (unsigned)(buf * TILE_H) * 2u;

        float s[8][4];
        #pragma unroll
        for (int nt = 0; nt < 8; nt++)
            #pragma unroll
            for (int q = 0; q < 4; q++) s[nt][q] = 0.f;
        {
            unsigned kAddr = kbu + (unsigned)((lane & 7) * QST) * 2u
                           + (unsigned)((lane >> 3) & 1) * 16u;
            #pragma unroll
            for (int ks = 0; ks < 4; ks++) {
                unsigned koff = (unsigned)ks * 32u;
                #pragma unroll
                for (int nt = 0; nt < 8; nt++) {
                    unsigned b0, b1;
                    ldsm2(b0, b1, kAddr + (unsigned)(nt * 8 * QST) * 2u + koff);
                    mma_f16(s[nt], aq[ks][0], aq[ks][1], aq[ks][2], aq[ks][3], b0, b1);
                }
            }
        }

        const float sc = 0.125f;
        float mx0 = -1e30f, mx1 = -1e30f;
        #pragma unroll
        for (int nt = 0; nt < 8; nt++) {
            s[nt][0] *= sc; s[nt][1] *= sc; s[nt][2] *= sc; s[nt][3] *= sc;
            mx0 = fmaxf(mx0, fmaxf(s[nt][0], s[nt][1]));
            mx1 = fmaxf(mx1, fmaxf(s[nt][2], s[nt][3]));
        }
        mx0 = fmaxf(mx0, __shfl_xor_sync(0xffffffffu, mx0, 1));
        mx0 = fmaxf(mx0, __shfl_xor_sync(0xffffffffu, mx0, 2));
        mx1 = fmaxf(mx1, __shfl_xor_sync(0xffffffffu, mx1, 1));
        mx1 = fmaxf(mx1, __shfl_xor_sync(0xffffffffu, mx1, 2));
        float mn0 = fmaxf(mr0, mx0), mn1 = fmaxf(mr1, mx1);
        float a0 = __expf(mr0 - mn0), a1 = __expf(mr1 - mn1);
        float sum0 = 0.f, sum1 = 0.f;
        #pragma unroll
        for (int nt = 0; nt < 8; nt++) {
            s[nt][0] = __expf(s[nt][0] - mn0);
            s[nt][1] = __expf(s[nt][1] - mn0);
            s[nt][2] = __expf(s[nt][2] - mn1);
            s[nt][3] = __expf(s[nt][3] - mn1);
            sum0 += s[nt][0] + s[nt][1];
            sum1 += s[nt][2] + s[nt][3];
        }
        sum0 += __shfl_xor_sync(0xffffffffu, sum0, 1);
        sum0 += __shfl_xor_sync(0xffffffffu, sum0, 2);
        sum1 += __shfl_xor_sync(0xffffffffu, sum1, 1);
        sum1 += __shfl_xor_sync(0xffffffffu, sum1, 2);
        lr0 = lr0 * a0 + sum0;
        lr1 = lr1 * a1 + sum1;
        mr0 = mn0; mr1 = mn1;
        #pragma unroll
        for (int nt = 0; nt < 8; nt++) {
            o[nt][0] *= a0; o[nt][1] *= a0;
            o[nt][2] *= a1; o[nt][3] *= a1;
        }

        __half* Ps = Qs;
        #pragma unroll
        for (int nt = 0; nt < 8; nt++) {
            int cc = nt * 8 + tg * 2;
            *(__half2*)&Ps[(wm + gid) * QST + cc]     = f2h2(s[nt][0], s[nt][1]);
            *(__half2*)&Ps[(wm + gid + 8) * QST + cc] = f2h2(s[nt][2], s[nt][3]);
        }
        __syncwarp();

        {
            unsigned pAddr = qsu + (unsigned)((wm + (lane & 15)) * QST) * 2u
                           + (unsigned)(lane >> 4) * 16u;
            unsigned vRow = (unsigned)((lane & 7) + ((lane >> 3) & 1) * 8);
            #pragma unroll
            for (int ks = 0; ks < 4; ks++) {
                unsigned pf0, pf1, pf2, pf3;
                ldsm4(pf0, pf1, pf2, pf3, pAddr + (unsigned)ks * 32u);
                unsigned vBase = vbu + (unsigned)((ks * 16 + vRow) * QST) * 2u;
                #pragma unroll
                for (int nt = 0; nt < 8; nt++) {
                    unsigned v0, v1;
                    ldsm2t(v0, v1, vBase + (unsigned)(nt * 8) * 2u);
                    mma_f16(o[nt], pf0, pf1, pf2, pf3, v0, v1);
                }
            }
        }
        __syncthreads();
    }

    float inv0 = 1.0f / lr0, inv1 = 1.0f / lr1;
    int rA = b * Sq + m0 + wm + gid, rB = rA + 8;
    #pragma unroll
    for (int nt = 0; nt < 8; nt++) {
        int cc = h * HDm + nt * 8 + tg * 2;
        *(__half2*)&O[(size_t)rA * Dm + cc] = f2h2(o[nt][0] * inv0, o[nt][1] * inv0);
        *(__half2*)&O[(size_t)rB * Dm + cc] = f2h2(o[nt][2] * inv1, o[nt][3] * inv1);
    }
}

// ---------------- router (exact fp32 logits) ----------------------------------
__global__ void route_kernel(const float* __restrict__ H2,
                             const float* __restrict__ SW,
                             const float* __restrict__ SB) {
    int warp = (blockIdx.x * blockDim.x + threadIdx.x) >> 5;
    int lane = threadIdx.x & 31;
    if (warp >= TOK) return;
    const float* hrow = H2 + (size_t)warp * Dm;
    float acc[En];
    #pragma unroll
    for (int e = 0; e < En; e++) acc[e] = 0.f;
    for (int d = lane; d < Dm; d += 32) {
        float hv = hrow[d];
        const float* w = SW + d * En;
        #pragma unroll
        for (int e = 0; e < En; e++) acc[e] += hv * w[e];
    }
    #pragma unroll
    for (int e = 0; e < En; e++)
        #pragma unroll
        for (int o = 16; o; o >>= 1)
            acc[e] += __shfl_xor_sync(0xffffffffu, acc[e], o);
    if (lane == 0) {
        float best = acc[0] + SB[0];
        int be = 0;
        #pragma unroll
        for (int e = 1; e < En; e++) {
            float v = acc[e] + SB[e];
            if (v > best) { best = v; be = e; }
        }
        g_routes[warp] = be;
        atomicAdd(&g_cnt[be], 1);
    }
}

__global__ void offsets_kernel() {
    if (threadIdx.x == 0) {
        int acc = 0;
        for (int e = 0; e < En; e++) { g_off[e] = acc; acc += g_cnt[e]; }
    }
}

__global__ void scatter_kernel() {
    int t = blockIdx.x * blockDim.x + threadIdx.x;
    if (t >= TOK) return;
    int e = g_routes[t];
    int pos = atomicAdd(&g_cur[e], 1);
    g_sorted[g_off[e] + pos] = t;
}

// ---------------- launch ------------------------------------------------------
extern "C" void kernel_launch(void* const* d_in, const int* in_sizes, int n_in,
                              void* d_out, int out_size) {
    const float* x       = (const float*)d_in[0];
    // d_in[1] = indexes_list (unused by reference math)
    const float* ln1_g   = (const float*)d_in[2];
    const float* ln1_b   = (const float*)d_in[3];
    const float* qkv_w   = (const float*)d_in[4];
    const float* proj_w  = (const float*)d_in[5];
    const float* proj_b  = (const float*)d_in[6];
    const float* ln2_g   = (const float*)d_in[7];
    const float* ln2_b   = (const float*)d_in[8];
    const float* sw_w    = (const float*)d_in[9];
    const float* sw_b    = (const float*)d_in[10];
    const float* w1      = (const float*)d_in[11];
    const float* b1      = (const float*)d_in[12];
    const float* w2      = (const float*)d_in[13];
    const float* b2      = (const float*)d_in[14];
    float* out = (float*)d_out;

    __half *gh, *gqkv, *go, *ghh, *gy1, *gqT, *gpT, *g1T, *g2T;
    float *gh2;
    cudaGetSymbolAddress((void**)&gh,   g_h);
    cudaGetSymbolAddress((void**)&gqkv, g_qkv);
    cudaGetSymbolAddress((void**)&go,   g_o);
    cudaGetSymbolAddress((void**)&gh2,  g_h2);
    cudaGetSymbolAddress((void**)&ghh,  g_hh);
    cudaGetSymbolAddress((void**)&gy1,  g_y1);
    cudaGetSymbolAddress((void**)&gqT,  g_qkvT);
    cudaGetSymbolAddress((void**)&gpT,  g_projT);
    cudaGetSymbolAddress((void**)&g1T,  g_w1T);
    cudaGetSymbolAddress((void**)&g2T,  g_w2T);

    static cudaStream_t s2 = nullptr;
    static cudaEvent_t evFork = nullptr, evW = nullptr;
    static int init_done = 0;
    if (!init_done) {
        cudaStreamCreateWithFlags(&s2, cudaStreamNonBlocking);
        cudaEventCreateWithFlags(&evFork, cudaEventDisableTiming);
        cudaEventCreateWithFlags(&evW,    cudaEventDisableTiming);
        cudaFuncSetAttribute(flash_f16, cudaFuncAttributeMaxDynamicSharedMemorySize, FA_SMEM);
        cudaFuncSetAttribute(gemm_f16,  cudaFuncAttributeMaxDynamicSharedMemorySize, GEMM_SMEM_H);
        cudaFuncSetAttribute(moe1_f16,  cudaFuncAttributeMaxDynamicSharedMemorySize, GEMM_SMEM_H);
        cudaFuncSetAttribute(moe2_f16,  cudaFuncAttributeMaxDynamicSharedMemorySize, GEMM_SMEM_H);
        init_done = 1;
    }

    reset_kernel<<<1, 32>>>();

    // ---- fork side stream: big weight transposes (consumed late) ----
    cudaEventRecord(evFork, 0);
    cudaStreamWaitEvent(s2, evFork, 0);
    transpose_h<<<dim3(Dm / 32, Dm / 32), dim3(32, 8), 0, s2>>>(proj_w, gpT, Dm, Dm);
    transpose_h<<<dim3(FFd / 32, Dm / 32, En), dim3(32, 8), 0, s2>>>(w1, g1T, Dm, FFd);
    transpose_h<<<dim3(Dm / 32, FFd / 32, En), dim3(32, 8), 0, s2>>>(w2, g2T, FFd, Dm);
    cudaEventRecord(evW, s2);

    // ---- main stream: critical path ----
    transpose_h<<<dim3(3 * Dm / 32, Dm / 32), dim3(32, 8)>>>(qkv_w, gqT, Dm, 3 * Dm);
    ln_kernel<<<TOK, 256>>>(x, ln1_g, ln1_b, nullptr, gh);
    gemm_f16<<<dim3(3 * Dm / 128, TOK / 128), 256, GEMM_SMEM_H>>>(
        gh, gqT, nullptr, gqkv, 3 * Dm, Dm, nullptr, nullptr);
    flash_f16<<<dim3(Sq / 64, BHN), 128, FA_SMEM>>>(gqkv, go);

    // join: proj needs projT; moe needs w1T/w2T (all on s2)
    cudaStreamWaitEvent(0, evW, 0);

    gemm_f16<<<dim3(Dm / 128, TOK / 128), 256, GEMM_SMEM_H>>>(
        go, gpT, out, nullptr, Dm, Dm, proj_b, x);
    ln_kernel<<<TOK, 256>>>(out, ln2_g, ln2_b, gh2, ghh);
    route_kernel<<<512, 256>>>(gh2, sw_w, sw_b);
    offsets_kernel<<<1, 32>>>();
    scatter_kernel<<<TOK / 256, 256>>>();
    moe1_f16<<<dim3(FFd / 128, TOK / 128, En), 256, GEMM_SMEM_H>>>(ghh, g1T, b1, gy1);
    moe2_f16<<<dim3(Dm / 128, TOK / 128, En), 256, GEMM_SMEM_H>>>(gy1, g2T, b2, out);
}